// round 1
// baseline (speedup 1.0000x reference)
#include <cuda_runtime.h>
#include <math.h>

// Problem constants (fixed by the reference)
constexpr int Bb = 4, TiC = 512, TjC = 512, NHc = 64, Dc = 512;
constexpr int NHEADS = Bb * NHc;        // 256
constexpr int MPROJ  = Bb * TiC * NHc;  // 131072

// Scratch (device globals; no cudaMalloc allowed)
__device__ float g_Q[(size_t)NHEADS * TiC * Dc];  // [B,N,Ti,D]
__device__ float g_K[(size_t)NHEADS * TjC * Dc];  // [B,N,Tj,D]
__device__ float g_V[(size_t)NHEADS * TjC * Dc];  // [B,N,Tj,D]
__device__ float g_S[(size_t)NHEADS * TiC * TjC]; // [B,N,Ti,Tj]

// One tiled fp32 GEMM body, three epilogues.
// MODE 0: proj  C = X @ W^T + b   (NT), store transposed to [B,N,T,D] scratch
// MODE 1: qk    S = scale * Q @ K^T + decay_log(t,s)   per head (NT)
// MODE 2: pv    O = P @ V  per head (NN), store to out[b,t,n,d]
// Tiles: BM=BN=128, BK=16, 256 threads, 8x8 micro-tile per thread.
template<int MODE>
__global__ __launch_bounds__(256, 1)
void gemm_kernel(const float* __restrict__ Ag, const float* __restrict__ Bg,
                 const float* __restrict__ bias, float* __restrict__ Outg,
                 const float* __restrict__ lgptr, const float* __restrict__ ltptr,
                 int which)
{
    __shared__ float As[16][128];
    __shared__ float Bs[16][128];
    const int tid = threadIdx.x;
    const int tx = tid & 15, ty = tid >> 4;
    const int m0 = blockIdx.x * 128;
    const int n0 = blockIdx.y * 128;
    const int h  = blockIdx.z;

    const float* A;
    const float* Bp;
    if constexpr (MODE == 0) { A = Ag; Bp = Bg; }
    else if constexpr (MODE == 1) {
        A  = g_Q + (size_t)h * TiC * Dc;
        Bp = g_K + (size_t)h * TjC * Dc;
    } else {
        A  = g_S + (size_t)h * TiC * TjC;
        Bp = g_V + (size_t)h * TjC * Dc;
    }

    float acc[8][8];
#pragma unroll
    for (int i = 0; i < 8; i++)
#pragma unroll
        for (int j = 0; j < 8; j++) acc[i][j] = 0.f;

    for (int k0 = 0; k0 < 512; k0 += 16) {
#pragma unroll
        for (int it = 0; it < 2; it++) {
            int v  = tid + it * 256;   // 0..511
            int r  = v >> 2;           // 0..127 row in tile
            int kq = (v & 3) << 2;     // 0,4,8,12
            float4 a = *(const float4*)(A + (size_t)(m0 + r) * 512 + k0 + kq);
            As[kq + 0][r] = a.x; As[kq + 1][r] = a.y;
            As[kq + 2][r] = a.z; As[kq + 3][r] = a.w;
            if constexpr (MODE != 2) {
                // NT: B is [N,512] row-major, k contiguous
                float4 b = *(const float4*)(Bp + (size_t)(n0 + r) * 512 + k0 + kq);
                Bs[kq + 0][r] = b.x; Bs[kq + 1][r] = b.y;
                Bs[kq + 2][r] = b.z; Bs[kq + 3][r] = b.w;
            } else {
                // NN: B is [K,512] row-major, n contiguous
                int kk = v >> 5;            // 0..15
                int nq = (v & 31) << 2;     // 0..124
                *(float4*)&Bs[kk][nq] =
                    *(const float4*)(Bp + (size_t)(k0 + kk) * 512 + n0 + nq);
            }
        }
        __syncthreads();
#pragma unroll
        for (int k = 0; k < 16; k++) {
            float4 a0 = *(const float4*)&As[k][ty * 4];
            float4 a1 = *(const float4*)&As[k][ty * 4 + 64];
            float4 b0 = *(const float4*)&Bs[k][tx * 4];
            float4 b1 = *(const float4*)&Bs[k][tx * 4 + 64];
            float av[8] = {a0.x, a0.y, a0.z, a0.w, a1.x, a1.y, a1.z, a1.w};
            float bv[8] = {b0.x, b0.y, b0.z, b0.w, b1.x, b1.y, b1.z, b1.w};
#pragma unroll
            for (int i = 0; i < 8; i++)
#pragma unroll
                for (int j = 0; j < 8; j++)
                    acc[i][j] = fmaf(av[i], bv[j], acc[i][j]);
        }
        __syncthreads();
    }

    int rows[8];
#pragma unroll
    for (int i = 0; i < 8; i++) rows[i] = ((i & 4) ? 64 : 0) + ty * 4 + (i & 3);
    const int cols2[2] = { tx * 4, 64 + tx * 4 };

    if constexpr (MODE == 0) {
        float* OutT = (which == 0) ? g_Q : (which == 1) ? g_K : g_V;
        float bvals[8];
#pragma unroll
        for (int jq = 0; jq < 2; jq++)
#pragma unroll
            for (int j = 0; j < 4; j++)
                bvals[jq * 4 + j] = bias[n0 + cols2[jq] + j];
#pragma unroll
        for (int i = 0; i < 8; i++) {
            int m = m0 + rows[i];           // m = ((b*Ti + t)*NH + n)
            int b = m >> 15;                // / (Ti*NH)
            int t = (m >> 6) & 511;
            int n = m & 63;
            float* dst = OutT + ((size_t)((b * NHc + n) * TiC + t)) * 512;
#pragma unroll
            for (int jq = 0; jq < 2; jq++) {
                float4 v;
                v.x = acc[i][jq * 4 + 0] + bvals[jq * 4 + 0];
                v.y = acc[i][jq * 4 + 1] + bvals[jq * 4 + 1];
                v.z = acc[i][jq * 4 + 2] + bvals[jq * 4 + 2];
                v.w = acc[i][jq * 4 + 3] + bvals[jq * 4 + 3];
                *(float4*)(dst + n0 + cols2[jq]) = v;
            }
        }
    } else if constexpr (MODE == 1) {
        float tau   = fmaxf(expf(*ltptr), 0.01f);
        float gamma = fmaxf(expf(*lgptr), 0.01f);
        float scale = 1.0f / (sqrtf(512.0f) * tau);
        float* Sh = g_S + (size_t)h * TiC * TjC;
#pragma unroll
        for (int i = 0; i < 8; i++) {
            int t = m0 + rows[i];
            float tif = t * (1.0f / 511.0f);
            float* dst = Sh + (size_t)t * TjC;
#pragma unroll
            for (int jq = 0; jq < 2; jq++) {
                float4 v;
#pragma unroll
                for (int j = 0; j < 4; j++) {
                    int s = n0 + cols2[jq] + j;
                    float d  = fabsf(tif - s * (1.0f / 511.0f));
                    float dl = logf(expf(-gamma * d) + 1e-8f);
                    ((float*)&v)[j] = acc[i][jq * 4 + j] * scale + dl;
                }
                *(float4*)(dst + n0 + cols2[jq]) = v;
            }
        }
    } else {
        int b = h >> 6;       // / NH
        int n = h & 63;
#pragma unroll
        for (int i = 0; i < 8; i++) {
            int t = m0 + rows[i];
            float* dst = Outg + ((size_t)((b * TiC + t) * NHc + n)) * 512;
#pragma unroll
            for (int jq = 0; jq < 2; jq++) {
                float4 v;
                v.x = acc[i][jq * 4 + 0];
                v.y = acc[i][jq * 4 + 1];
                v.z = acc[i][jq * 4 + 2];
                v.w = acc[i][jq * 4 + 3];
                *(float4*)(dst + n0 + cols2[jq]) = v;
            }
        }
    }
}

// Row softmax over Tj=512. One block (128 threads, 4 elems/thread) per row.
__global__ __launch_bounds__(128)
void softmax_kernel()
{
    __shared__ float red[8];
    size_t row = blockIdx.x;
    float* p = g_S + row * 512;
    int tid = threadIdx.x;
    float4 v = *((float4*)p + tid);
    float mx = fmaxf(fmaxf(v.x, v.y), fmaxf(v.z, v.w));
#pragma unroll
    for (int o = 16; o; o >>= 1) mx = fmaxf(mx, __shfl_xor_sync(0xffffffffu, mx, o));
    if ((tid & 31) == 0) red[tid >> 5] = mx;
    __syncthreads();
    mx = fmaxf(fmaxf(red[0], red[1]), fmaxf(red[2], red[3]));
    v.x = __expf(v.x - mx);
    v.y = __expf(v.y - mx);
    v.z = __expf(v.z - mx);
    v.w = __expf(v.w - mx);
    float s = v.x + v.y + v.z + v.w;
#pragma unroll
    for (int o = 16; o; o >>= 1) s += __shfl_xor_sync(0xffffffffu, s, o);
    if ((tid & 31) == 0) red[4 + (tid >> 5)] = s;
    __syncthreads();
    s = red[4] + red[5] + red[6] + red[7];
    float inv = 1.0f / s;
    v.x *= inv; v.y *= inv; v.z *= inv; v.w *= inv;
    *((float4*)p + tid) = v;
}

extern "C" void kernel_launch(void* const* d_in, const int* in_sizes, int n_in,
                              void* d_out, int out_size)
{
    const float* H_i = (const float*)d_in[0];
    const float* H_j = (const float*)d_in[1];
    const float* Wq  = (const float*)d_in[2];
    const float* bq  = (const float*)d_in[3];
    const float* Wk  = (const float*)d_in[4];
    const float* bk  = (const float*)d_in[5];
    const float* Wv  = (const float*)d_in[6];
    const float* bv  = (const float*)d_in[7];
    const float* lg  = (const float*)d_in[8];
    const float* lt  = (const float*)d_in[9];
    float* out = (float*)d_out;

    dim3 blk(256);
    dim3 gproj(MPROJ / 128, Dc / 128, 1);       // (1024, 4)
    gemm_kernel<0><<<gproj, blk>>>(H_i, Wq, bq, nullptr, nullptr, nullptr, 0);
    gemm_kernel<0><<<gproj, blk>>>(H_j, Wk, bk, nullptr, nullptr, nullptr, 1);
    gemm_kernel<0><<<gproj, blk>>>(H_j, Wv, bv, nullptr, nullptr, nullptr, 2);

    dim3 ghead(TiC / 128, TjC / 128, NHEADS);   // (4, 4, 256)
    gemm_kernel<1><<<ghead, blk>>>(nullptr, nullptr, nullptr, nullptr, lg, lt, 0);

    softmax_kernel<<<NHEADS * TiC, 128>>>();

    gemm_kernel<2><<<ghead, blk>>>(nullptr, nullptr, nullptr, out, nullptr, nullptr, 0);
}

// round 3
// speedup vs baseline: 1.6062x; 1.6062x over previous
#include <cuda_runtime.h>
#include <cstdint>
#include <math.h>

constexpr int Tt = 512, NHc = 64, Dd = 512, Bb = 4;
constexpr int NHEADS = Bb * NHc;        // 256
constexpr int MPROJ  = Bb * Tt * NHc;   // 131072
constexpr int SMS    = 136;             // smem row stride (floats); 136 mod 32 = 8 -> conflict-free frags

// Scratch (device globals; no cudaMalloc allowed)
__device__ float g_Q [(size_t)MPROJ * Dd];       // [B,T,N,D] natural
__device__ float g_K [(size_t)MPROJ * Dd];       // [B,T,N,D]
__device__ float g_V [(size_t)MPROJ * Dd];       // [B,T,N,D]
__device__ float g_Vt[(size_t)NHEADS * Dd * Tt]; // [B,N,D,S]
__device__ float g_S [(size_t)NHEADS * Tt * Tt]; // [B,N,T,S]

__device__ __forceinline__ float f2tf32(float x) {
    float r;
    asm("cvt.rna.tf32.f32 %0, %1;" : "=f"(r) : "f"(x));
    return r;
}
__device__ __forceinline__ float4 f4tf32(float4 v) {
    v.x = f2tf32(v.x); v.y = f2tf32(v.y); v.z = f2tf32(v.z); v.w = f2tf32(v.w);
    return v;
}
__device__ __forceinline__ void mma_tf32(float& d0, float& d1, float& d2, float& d3,
                                         uint32_t a0, uint32_t a1, uint32_t a2, uint32_t a3,
                                         uint32_t b0, uint32_t b1) {
    asm volatile(
        "mma.sync.aligned.m16n8k8.row.col.f32.tf32.tf32.f32 "
        "{%0,%1,%2,%3}, {%4,%5,%6,%7}, {%8,%9}, {%0,%1,%2,%3};"
        : "+f"(d0), "+f"(d1), "+f"(d2), "+f"(d3)
        : "r"(a0), "r"(a1), "r"(a2), "r"(a3), "r"(b0), "r"(b1));
}

// ---------------- Generic tf32 mma.sync GEMM ----------------
// All modes are NT with k-contiguous rows (possibly strided):
// MODE 0: proj  C[m,n] = H[m,:]@W[n,:] + b[n]  -> g_Q/g_K/g_V (natural [B,T,N,D])
// MODE 1: qk    S = scale*Q@K^T + decay_log    per head (rows strided 32768)
// MODE 2: pv    O = P@Vt^T                     per head -> out[b,t,n,d]
// Tile 128x128, K=512 in 16 stages of BK=32, double-buffered padded SMEM,
// 256 threads = 8 warps as 2(m)x4(n); warp tile 64x32; per-thread acc 4x4x4.
template<int MODE>
__global__ __launch_bounds__(256, 2)
void mma_gemm(const float* __restrict__ Ag, const float* __restrict__ Bg,
              const float* __restrict__ bias, float* __restrict__ Outg,
              const float* __restrict__ lg, const float* __restrict__ lt,
              int which)
{
    extern __shared__ float sm[];   // [2 buffers][A:32x136 | B:32x136]

    const int tid  = threadIdx.x;
    const int wid  = tid >> 5, lane = tid & 31;
    const int wm   = wid >> 2;          // 0..1
    const int wn   = wid & 3;           // 0..3
    const int kq   = lane & 3;          // k within frag
    const int rq   = lane >> 2;         // row/col within frag
    const int m0   = blockIdx.x * 128;
    const int n0   = blockIdx.y * 128;
    const int h    = blockIdx.z;

    const float *A, *B;
    size_t sA, sB;  // row strides in floats
    if constexpr (MODE == 0) {
        A = Ag + (size_t)m0 * 512; sA = 512;
        B = Bg + (size_t)n0 * 512; sB = 512;
    } else if constexpr (MODE == 1) {
        int b = h >> 6, n = h & 63;
        size_t base = ((size_t)b * 32768 + (size_t)n) * 512;
        A = g_Q + base + (size_t)m0 * 32768; sA = 32768;
        B = g_K + base + (size_t)n0 * 32768; sB = 32768;
    } else {
        A = g_S  + (size_t)h * (Tt * Tt) + (size_t)m0 * 512; sA = 512;
        B = g_Vt + (size_t)h * (Dd * Tt) + (size_t)n0 * 512; sB = 512;
    }

    // gmem staging: thread owns row (tid&127), chunks c = (tid>>7) + 2i (i=0..3)
    const int srow = tid & 127;
    const int c0   = tid >> 7;
    const float* arow = A + (size_t)srow * sA;
    const float* brow = B + (size_t)srow * sB;

    float4 ra[4], rbv[4];
    auto ldstage = [&](int s) {
#pragma unroll
        for (int i = 0; i < 4; i++) {
            int c = c0 + 2 * i;
            ra [i] = f4tf32(*(const float4*)(arow + s * 32 + c * 4));
            rbv[i] = f4tf32(*(const float4*)(brow + s * 32 + c * 4));
        }
    };
    auto ststage = [&](int buf) {
        float* As = sm + buf * (2 * 32 * SMS);
        float* Bs = As + 32 * SMS;
#pragma unroll
        for (int i = 0; i < 4; i++) {
            int c = c0 + 2 * i;
#pragma unroll
            for (int j = 0; j < 4; j++) {
                As[(c * 4 + j) * SMS + srow] = ((const float*)&ra [i])[j];
                Bs[(c * 4 + j) * SMS + srow] = ((const float*)&rbv[i])[j];
            }
        }
    };

    float acc[4][4][4];
#pragma unroll
    for (int mt = 0; mt < 4; mt++)
#pragma unroll
        for (int nt = 0; nt < 4; nt++)
#pragma unroll
            for (int e = 0; e < 4; e++) acc[mt][nt][e] = 0.f;

    const int mfrag = wm * 64;     // warp m base within tile
    const int nfrag = wn * 32;     // warp n base within tile

    ldstage(0);
    for (int s = 0; s < 16; s++) {
        const int buf = s & 1;
        ststage(buf);
        __syncthreads();
        if (s + 1 < 16) ldstage(s + 1);

        const float* As = sm + buf * (2 * 32 * SMS);
        const float* Bs = As + 32 * SMS;
#pragma unroll
        for (int ks = 0; ks < 4; ks++) {
            const int kb = ks * 8;
            uint32_t afr[4][4], bfr[4][2];
#pragma unroll
            for (int mt = 0; mt < 4; mt++) {
                const int mb = mfrag + mt * 16;
                afr[mt][0] = __float_as_uint(As[(kb + kq)     * SMS + mb + rq]);
                afr[mt][1] = __float_as_uint(As[(kb + kq)     * SMS + mb + rq + 8]);
                afr[mt][2] = __float_as_uint(As[(kb + kq + 4) * SMS + mb + rq]);
                afr[mt][3] = __float_as_uint(As[(kb + kq + 4) * SMS + mb + rq + 8]);
            }
#pragma unroll
            for (int nt = 0; nt < 4; nt++) {
                const int nb = nfrag + nt * 8;
                bfr[nt][0] = __float_as_uint(Bs[(kb + kq)     * SMS + nb + rq]);
                bfr[nt][1] = __float_as_uint(Bs[(kb + kq + 4) * SMS + nb + rq]);
            }
#pragma unroll
            for (int mt = 0; mt < 4; mt++)
#pragma unroll
                for (int nt = 0; nt < 4; nt++)
                    mma_tf32(acc[mt][nt][0], acc[mt][nt][1], acc[mt][nt][2], acc[mt][nt][3],
                             afr[mt][0], afr[mt][1], afr[mt][2], afr[mt][3],
                             bfr[nt][0], bfr[nt][1]);
        }
        __syncthreads();
    }

    // ---------------- epilogues ----------------
    // acc[mt][nt]: c0 -> (r, c), c1 -> (r, c+1), c2 -> (r+8, c), c3 -> (r+8, c+1)
    // r = mfrag + mt*16 + rq (tile row), c = nfrag + nt*8 + kq*2 (tile col)
    if constexpr (MODE == 0) {
        float* outp = (which == 0) ? g_Q : (which == 1) ? g_K : g_V;
#pragma unroll
        for (int mt = 0; mt < 4; mt++) {
            const int r = m0 + mfrag + mt * 16 + rq;
#pragma unroll
            for (int nt = 0; nt < 4; nt++) {
                const int c = n0 + nfrag + nt * 8 + kq * 2;
                float2 bv = *(const float2*)(bias + c);
                float2 v0 = { acc[mt][nt][0] + bv.x, acc[mt][nt][1] + bv.y };
                float2 v1 = { acc[mt][nt][2] + bv.x, acc[mt][nt][3] + bv.y };
                *(float2*)(outp + (size_t)r * 512 + c)       = v0;
                *(float2*)(outp + (size_t)(r + 8) * 512 + c) = v1;
            }
        }
    } else if constexpr (MODE == 1) {
        const float gamma = fmaxf(__expf(*lg), 0.01f);
        const float tau   = fmaxf(__expf(*lt), 0.01f);
        const float scale = 1.0f / (22.62741699796952f * tau);
        float* Sh = g_S + (size_t)h * (Tt * Tt);
#pragma unroll
        for (int mt = 0; mt < 4; mt++) {
            const int r = m0 + mfrag + mt * 16 + rq;
#pragma unroll
            for (int nt = 0; nt < 4; nt++) {
                const int c = n0 + nfrag + nt * 8 + kq * 2;
#pragma unroll
                for (int half = 0; half < 2; half++) {
                    const int t = r + half * 8;
                    float2 v;
#pragma unroll
                    for (int e = 0; e < 2; e++) {
                        float gd = gamma * fabsf((float)(t - (c + e))) * (1.0f / 511.0f);
                        float dl = (gd < 11.0f) ? -gd : logf(expf(-gd) + 1e-8f);
                        ((float*)&v)[e] = acc[mt][nt][half * 2 + e] * scale + dl;
                    }
                    *(float2*)(Sh + (size_t)t * 512 + c) = v;
                }
            }
        }
    } else {
        const int b = h >> 6, n = h & 63;
#pragma unroll
        for (int mt = 0; mt < 4; mt++) {
            const int r = m0 + mfrag + mt * 16 + rq;
#pragma unroll
            for (int nt = 0; nt < 4; nt++) {
                const int c = n0 + nfrag + nt * 8 + kq * 2;
#pragma unroll
                for (int half = 0; half < 2; half++) {
                    const int t = r + half * 8;
                    float2 v = { acc[mt][nt][half * 2 + 0], acc[mt][nt][half * 2 + 1] };
                    *(float2*)(Outg + (((size_t)(b * Tt + t) * NHc + n) << 9) + c) = v;
                }
            }
        }
    }
}

// ---------------- V transpose: [B,S,N,D] -> [(B,N),D,S] ----------------
__global__ __launch_bounds__(256)
void transpose_v()
{
    __shared__ float tile[32][33];
    const int h = blockIdx.z;
    const int b = h >> 6, n = h & 63;
    const int s0 = blockIdx.x * 32;
    const int d0 = blockIdx.y * 32;
    const float* src = g_V + ((size_t)b * 32768 + (size_t)n) * 512;
#pragma unroll
    for (int i = threadIdx.y; i < 32; i += 8)
        tile[i][threadIdx.x] = src[(size_t)(s0 + i) * 32768 + d0 + threadIdx.x];
    __syncthreads();
    float* dst = g_Vt + ((size_t)h * Dd + d0) * Tt + s0;
#pragma unroll
    for (int i = threadIdx.y; i < 32; i += 8)
        dst[(size_t)i * Tt + threadIdx.x] = tile[threadIdx.x][i];
}

// ---------------- Row softmax over Tj=512 ----------------
__global__ __launch_bounds__(128)
void softmax_kernel()
{
    __shared__ float red[8];
    size_t row = blockIdx.x;
    float* p = g_S + row * 512;
    int tid = threadIdx.x;
    float4 v = *((float4*)p + tid);
    float mx = fmaxf(fmaxf(v.x, v.y), fmaxf(v.z, v.w));
#pragma unroll
    for (int o = 16; o; o >>= 1) mx = fmaxf(mx, __shfl_xor_sync(0xffffffffu, mx, o));
    if ((tid & 31) == 0) red[tid >> 5] = mx;
    __syncthreads();
    mx = fmaxf(fmaxf(red[0], red[1]), fmaxf(red[2], red[3]));
    v.x = __expf(v.x - mx);
    v.y = __expf(v.y - mx);
    v.z = __expf(v.z - mx);
    v.w = __expf(v.w - mx);
    float s = v.x + v.y + v.z + v.w;
#pragma unroll
    for (int o = 16; o; o >>= 1) s += __shfl_xor_sync(0xffffffffu, s, o);
    if ((tid & 31) == 0) red[4 + (tid >> 5)] = s;
    __syncthreads();
    s = red[4] + red[5] + red[6] + red[7];
    float inv = 1.0f / s;
    v.x *= inv; v.y *= inv; v.z *= inv; v.w *= inv;
    *((float4*)p + tid) = v;
}

extern "C" void kernel_launch(void* const* d_in, const int* in_sizes, int n_in,
                              void* d_out, int out_size)
{
    const float* H_i = (const float*)d_in[0];
    const float* H_j = (const float*)d_in[1];
    const float* Wq  = (const float*)d_in[2];
    const float* bq  = (const float*)d_in[3];
    const float* Wk  = (const float*)d_in[4];
    const float* bk  = (const float*)d_in[5];
    const float* Wv  = (const float*)d_in[6];
    const float* bv  = (const float*)d_in[7];
    const float* lg  = (const float*)d_in[8];
    const float* lt  = (const float*)d_in[9];
    float* out = (float*)d_out;

    const int shmem = 2 * 2 * 32 * SMS * 4;  // 69632 B
    cudaFuncSetAttribute(mma_gemm<0>, cudaFuncAttributeMaxDynamicSharedMemorySize, shmem);
    cudaFuncSetAttribute(mma_gemm<1>, cudaFuncAttributeMaxDynamicSharedMemorySize, shmem);
    cudaFuncSetAttribute(mma_gemm<2>, cudaFuncAttributeMaxDynamicSharedMemorySize, shmem);

    dim3 blk(256);
    dim3 gproj(MPROJ / 128, 4, 1);      // (1024, 4)
    mma_gemm<0><<<gproj, blk, shmem>>>(H_i, Wq, bq, nullptr, nullptr, nullptr, 0);
    mma_gemm<0><<<gproj, blk, shmem>>>(H_j, Wk, bk, nullptr, nullptr, nullptr, 1);
    mma_gemm<0><<<gproj, blk, shmem>>>(H_j, Wv, bv, nullptr, nullptr, nullptr, 2);

    transpose_v<<<dim3(16, 16, NHEADS), dim3(32, 8)>>>();

    dim3 ghead(4, 4, NHEADS);
    mma_gemm<1><<<ghead, blk, shmem>>>(nullptr, nullptr, nullptr, nullptr, lg, lt, 0);

    softmax_kernel<<<NHEADS * Tt, 128>>>();

    mma_gemm<2><<<ghead, blk, shmem>>>(nullptr, nullptr, nullptr, out, nullptr, nullptr, 0);
}

// round 4
// speedup vs baseline: 2.2622x; 1.4084x over previous
#include <cuda_runtime.h>
#include <cstdint>
#include <math.h>

constexpr int Tt = 512, NHc = 64, Dd = 512, Bb = 4;
constexpr int NHEADS = Bb * NHc;        // 256
constexpr int MPROJ  = Bb * Tt * NHc;   // 131072
constexpr int RPAD   = 36;              // smem row stride in floats (128B row + 16B pad)
constexpr int ATILE  = 128 * RPAD;      // floats per tile buffer (4608)

// Scratch (device globals; no cudaMalloc allowed)
__device__ float g_Hi[(size_t)MPROJ * Dd];       // tf32-rounded H_i
__device__ float g_Hj[(size_t)MPROJ * Dd];       // tf32-rounded H_j
__device__ float g_Wq[(size_t)Dd * Dd];
__device__ float g_Wk[(size_t)Dd * Dd];
__device__ float g_Wv[(size_t)Dd * Dd];
__device__ float g_Q [(size_t)MPROJ * Dd];       // [B,T,N,D], tf32-rounded
__device__ float g_K [(size_t)MPROJ * Dd];       // [B,T,N,D], tf32-rounded
__device__ float g_V [(size_t)MPROJ * Dd];       // [B,T,N,D], tf32-rounded
__device__ float g_Vt[(size_t)NHEADS * Dd * Tt]; // [B,N,D,S]
__device__ float g_S [(size_t)NHEADS * Tt * Tt]; // [B,N,T,S]

__device__ __forceinline__ float f2tf32(float x) {
    float r;
    asm("cvt.rna.tf32.f32 %0, %1;" : "=f"(r) : "f"(x));
    return r;
}
__device__ __forceinline__ uint32_t smem_u32(const void* p) {
    uint32_t a;
    asm("{ .reg .u64 t; cvta.to.shared.u64 t, %1; cvt.u32.u64 %0, t; }" : "=r"(a) : "l"(p));
    return a;
}
__device__ __forceinline__ void cp_async16(uint32_t saddr, const void* gptr) {
    asm volatile("cp.async.cg.shared.global [%0], [%1], 16;" :: "r"(saddr), "l"(gptr));
}
__device__ __forceinline__ void cp_commit() {
    asm volatile("cp.async.commit_group;" ::: "memory");
}
template<int N> __device__ __forceinline__ void cp_wait() {
    asm volatile("cp.async.wait_group %0;" :: "n"(N) : "memory");
}
__device__ __forceinline__ void mma_tf32(float& d0, float& d1, float& d2, float& d3,
                                         uint32_t a0, uint32_t a1, uint32_t a2, uint32_t a3,
                                         uint32_t b0, uint32_t b1) {
    asm volatile(
        "mma.sync.aligned.m16n8k8.row.col.f32.tf32.tf32.f32 "
        "{%0,%1,%2,%3}, {%4,%5,%6,%7}, {%8,%9}, {%0,%1,%2,%3};"
        : "+f"(d0), "+f"(d1), "+f"(d2), "+f"(d3)
        : "r"(a0), "r"(a1), "r"(a2), "r"(a3), "r"(b0), "r"(b1));
}

// ---------------- tf32 rounding pre-pass ----------------
__global__ __launch_bounds__(256)
void round_tf32(const float* __restrict__ src, float* __restrict__ dst, size_t n4)
{
    size_t i = (size_t)blockIdx.x * blockDim.x + threadIdx.x;
    size_t stride = (size_t)gridDim.x * blockDim.x;
    for (; i < n4; i += stride) {
        float4 v = ((const float4*)src)[i];
        v.x = f2tf32(v.x); v.y = f2tf32(v.y);
        v.z = f2tf32(v.z); v.w = f2tf32(v.w);
        ((float4*)dst)[i] = v;
    }
}

// ---------------- Generic tf32 mma.sync GEMM (cp.async staging) ----------------
// All inputs pre-rounded to tf32. All modes NT with k-contiguous rows:
// MODE 0: proj  C[m,n] = H[m,:]@W[n,:] + b[n]  -> g_Q/g_K/g_V (rounded store)
// MODE 1: qk    S = scale*Q@K^T + decay_log    per head (rows strided 32768)
// MODE 2: pv    O = P@Vt^T                     per head -> out[b,t,n,d]
// Tile 128x128, K=512 in 16 stages of BK=32, cp.async double-buffered smem.
// smem tile layout: row-major [m][k], row stride RPAD=36 floats.
template<int MODE>
__global__ __launch_bounds__(256, 2)
void mma_gemm(const float* __restrict__ Ag, const float* __restrict__ Bg,
              const float* __restrict__ bias, float* __restrict__ Outg,
              const float* __restrict__ lg, const float* __restrict__ lt,
              int which)
{
    extern __shared__ float sm[];   // [2][A:128x36 | B:128x36]
    const uint32_t smbase = smem_u32(sm);

    const int tid  = threadIdx.x;
    const int wid  = tid >> 5, lane = tid & 31;
    const int wm   = wid >> 2;          // 0..1
    const int wn   = wid & 3;           // 0..3
    const int kq   = lane & 3;          // k within frag
    const int rq   = lane >> 2;         // row/col within frag
    const int m0   = blockIdx.x * 128;
    const int n0   = blockIdx.y * 128;
    const int h    = blockIdx.z;

    const float *A, *B;
    size_t sA, sB;  // row strides in floats
    if constexpr (MODE == 0) {
        A = Ag + (size_t)m0 * 512; sA = 512;
        B = Bg + (size_t)n0 * 512; sB = 512;
    } else if constexpr (MODE == 1) {
        int b = h >> 6, n = h & 63;
        size_t base = ((size_t)b * 32768 + (size_t)n) * 512;
        A = g_Q + base + (size_t)m0 * 32768; sA = 32768;
        B = g_K + base + (size_t)n0 * 32768; sB = 32768;
    } else {
        A = g_S  + (size_t)h * (Tt * Tt) + (size_t)m0 * 512; sA = 512;
        B = g_Vt + (size_t)h * (Dd * Tt) + (size_t)n0 * 512; sB = 512;
    }

    // cp.async staging: thread -> row (tid>>1), 4 chunks of 16B at ch0=(tid&1)*4
    const int srow = tid >> 1;
    const int ch0  = (tid & 1) * 4;
    const float* agp = A + (size_t)srow * sA + ch0 * 4;
    const float* bgp = B + (size_t)srow * sB + ch0 * 4;
    const uint32_t soff = (uint32_t)(srow * RPAD + ch0 * 4) * 4;  // bytes

    auto issue = [&](int s) {
        const int buf = s & 1;
        uint32_t abase = smbase + (uint32_t)buf * (2 * ATILE * 4) + soff;
        uint32_t bbase = abase + ATILE * 4;
        const float* ag = agp + s * 32;
        const float* bg = bgp + s * 32;
#pragma unroll
        for (int i = 0; i < 4; i++) {
            cp_async16(abase + i * 16, ag + i * 4);
            cp_async16(bbase + i * 16, bg + i * 4);
        }
        cp_commit();
    };

    float acc[4][4][4];
#pragma unroll
    for (int mt = 0; mt < 4; mt++)
#pragma unroll
        for (int nt = 0; nt < 4; nt++)
#pragma unroll
            for (int e = 0; e < 4; e++) acc[mt][nt][e] = 0.f;

    const int mfrag = wm * 64;
    const int nfrag = wn * 32;

    issue(0);
    for (int s = 0; s < 16; s++) {
        if (s + 1 < 16) { issue(s + 1); cp_wait<1>(); }
        else            { cp_wait<0>(); }
        __syncthreads();

        const float* As = sm + (s & 1) * (2 * ATILE);
        const float* Bs = As + ATILE;
#pragma unroll
        for (int ks = 0; ks < 4; ks++) {
            const int kb = ks * 8;
            uint32_t afr[4][4], bfr[4][2];
#pragma unroll
            for (int mt = 0; mt < 4; mt++) {
                const int mb = mfrag + mt * 16;
                afr[mt][0] = __float_as_uint(As[(mb + rq)     * RPAD + kb + kq]);
                afr[mt][1] = __float_as_uint(As[(mb + rq + 8) * RPAD + kb + kq]);
                afr[mt][2] = __float_as_uint(As[(mb + rq)     * RPAD + kb + kq + 4]);
                afr[mt][3] = __float_as_uint(As[(mb + rq + 8) * RPAD + kb + kq + 4]);
            }
#pragma unroll
            for (int nt = 0; nt < 4; nt++) {
                const int nb = nfrag + nt * 8;
                bfr[nt][0] = __float_as_uint(Bs[(nb + rq) * RPAD + kb + kq]);
                bfr[nt][1] = __float_as_uint(Bs[(nb + rq) * RPAD + kb + kq + 4]);
            }
#pragma unroll
            for (int mt = 0; mt < 4; mt++)
#pragma unroll
                for (int nt = 0; nt < 4; nt++)
                    mma_tf32(acc[mt][nt][0], acc[mt][nt][1], acc[mt][nt][2], acc[mt][nt][3],
                             afr[mt][0], afr[mt][1], afr[mt][2], afr[mt][3],
                             bfr[nt][0], bfr[nt][1]);
        }
        __syncthreads();
    }

    // ---------------- epilogues ----------------
    // acc[mt][nt]: c0 -> (r, c), c1 -> (r, c+1), c2 -> (r+8, c), c3 -> (r+8, c+1)
    // r = mfrag + mt*16 + rq, c = nfrag + nt*8 + kq*2
    if constexpr (MODE == 0) {
        float* outp = (which == 0) ? g_Q : (which == 1) ? g_K : g_V;
#pragma unroll
        for (int mt = 0; mt < 4; mt++) {
            const int r = m0 + mfrag + mt * 16 + rq;
#pragma unroll
            for (int nt = 0; nt < 4; nt++) {
                const int c = n0 + nfrag + nt * 8 + kq * 2;
                float2 bv = *(const float2*)(bias + c);
                float2 v0 = { f2tf32(acc[mt][nt][0] + bv.x), f2tf32(acc[mt][nt][1] + bv.y) };
                float2 v1 = { f2tf32(acc[mt][nt][2] + bv.x), f2tf32(acc[mt][nt][3] + bv.y) };
                *(float2*)(outp + (size_t)r * 512 + c)       = v0;
                *(float2*)(outp + (size_t)(r + 8) * 512 + c) = v1;
            }
        }
    } else if constexpr (MODE == 1) {
        const float gamma = fmaxf(__expf(*lg), 0.01f);
        const float tau   = fmaxf(__expf(*lt), 0.01f);
        const float scale = 1.0f / (22.62741699796952f * tau);
        float* Sh = g_S + (size_t)h * (Tt * Tt);
#pragma unroll
        for (int mt = 0; mt < 4; mt++) {
            const int r = m0 + mfrag + mt * 16 + rq;
#pragma unroll
            for (int nt = 0; nt < 4; nt++) {
                const int c = n0 + nfrag + nt * 8 + kq * 2;
#pragma unroll
                for (int half = 0; half < 2; half++) {
                    const int t = r + half * 8;
                    float2 v;
#pragma unroll
                    for (int e = 0; e < 2; e++) {
                        float gd = gamma * fabsf((float)(t - (c + e))) * (1.0f / 511.0f);
                        float dl = (gd < 11.0f) ? -gd : logf(expf(-gd) + 1e-8f);
                        ((float*)&v)[e] = acc[mt][nt][half * 2 + e] * scale + dl;
                    }
                    *(float2*)(Sh + (size_t)t * 512 + c) = v;
                }
            }
        }
    } else {
        const int b = h >> 6, n = h & 63;
#pragma unroll
        for (int mt = 0; mt < 4; mt++) {
            const int r = m0 + mfrag + mt * 16 + rq;
#pragma unroll
            for (int nt = 0; nt < 4; nt++) {
                const int c = n0 + nfrag + nt * 8 + kq * 2;
#pragma unroll
                for (int half = 0; half < 2; half++) {
                    const int t = r + half * 8;
                    float2 v = { acc[mt][nt][half * 2 + 0], acc[mt][nt][half * 2 + 1] };
                    *(float2*)(Outg + (((size_t)(b * Tt + t) * NHc + n) << 9) + c) = v;
                }
            }
        }
    }
}

// ---------------- V transpose: [B,S,N,D] -> [(B,N),D,S] ----------------
__global__ __launch_bounds__(256)
void transpose_v()
{
    __shared__ float tile[32][33];
    const int h = blockIdx.z;
    const int b = h >> 6, n = h & 63;
    const int s0 = blockIdx.x * 32;
    const int d0 = blockIdx.y * 32;
    const float* src = g_V + ((size_t)b * 32768 + (size_t)n) * 512;
#pragma unroll
    for (int i = threadIdx.y; i < 32; i += 8)
        tile[i][threadIdx.x] = src[(size_t)(s0 + i) * 32768 + d0 + threadIdx.x];
    __syncthreads();
    float* dst = g_Vt + ((size_t)h * Dd + d0) * Tt + s0;
#pragma unroll
    for (int i = threadIdx.y; i < 32; i += 8)
        dst[(size_t)i * Tt + threadIdx.x] = tile[threadIdx.x][i];
}

// ---------------- Row softmax over Tj=512 (tf32-rounded output) ----------------
__global__ __launch_bounds__(128)
void softmax_kernel()
{
    __shared__ float red[8];
    size_t row = blockIdx.x;
    float* p = g_S + row * 512;
    int tid = threadIdx.x;
    float4 v = *((float4*)p + tid);
    float mx = fmaxf(fmaxf(v.x, v.y), fmaxf(v.z, v.w));
#pragma unroll
    for (int o = 16; o; o >>= 1) mx = fmaxf(mx, __shfl_xor_sync(0xffffffffu, mx, o));
    if ((tid & 31) == 0) red[tid >> 5] = mx;
    __syncthreads();
    mx = fmaxf(fmaxf(red[0], red[1]), fmaxf(red[2], red[3]));
    v.x = __expf(v.x - mx);
    v.y = __expf(v.y - mx);
    v.z = __expf(v.z - mx);
    v.w = __expf(v.w - mx);
    float s = v.x + v.y + v.z + v.w;
#pragma unroll
    for (int o = 16; o; o >>= 1) s += __shfl_xor_sync(0xffffffffu, s, o);
    if ((tid & 31) == 0) red[4 + (tid >> 5)] = s;
    __syncthreads();
    s = red[4] + red[5] + red[6] + red[7];
    float inv = 1.0f / s;
    v.x = f2tf32(v.x * inv); v.y = f2tf32(v.y * inv);
    v.z = f2tf32(v.z * inv); v.w = f2tf32(v.w * inv);
    *((float4*)p + tid) = v;
}

extern "C" void kernel_launch(void* const* d_in, const int* in_sizes, int n_in,
                              void* d_out, int out_size)
{
    const float* H_i = (const float*)d_in[0];
    const float* H_j = (const float*)d_in[1];
    const float* Wq  = (const float*)d_in[2];
    const float* bq  = (const float*)d_in[3];
    const float* Wk  = (const float*)d_in[4];
    const float* bk  = (const float*)d_in[5];
    const float* Wv  = (const float*)d_in[6];
    const float* bv  = (const float*)d_in[7];
    const float* lg  = (const float*)d_in[8];
    const float* lt  = (const float*)d_in[9];
    float* out = (float*)d_out;

    float *p_Hi, *p_Hj, *p_Wq, *p_Wk, *p_Wv;
    cudaGetSymbolAddress((void**)&p_Hi, g_Hi);
    cudaGetSymbolAddress((void**)&p_Hj, g_Hj);
    cudaGetSymbolAddress((void**)&p_Wq, g_Wq);
    cudaGetSymbolAddress((void**)&p_Wk, g_Wk);
    cudaGetSymbolAddress((void**)&p_Wv, g_Wv);

    // tf32 pre-rounding (H: 64M elems each -> 16M float4)
    round_tf32<<<8192, 256>>>(H_i, p_Hi, (size_t)MPROJ * Dd / 4);
    round_tf32<<<8192, 256>>>(H_j, p_Hj, (size_t)MPROJ * Dd / 4);
    round_tf32<<<256, 256>>>(Wq, p_Wq, (size_t)Dd * Dd / 4);
    round_tf32<<<256, 256>>>(Wk, p_Wk, (size_t)Dd * Dd / 4);
    round_tf32<<<256, 256>>>(Wv, p_Wv, (size_t)Dd * Dd / 4);

    const int shmem = 2 * 2 * ATILE * 4;  // 73728 B
    cudaFuncSetAttribute(mma_gemm<0>, cudaFuncAttributeMaxDynamicSharedMemorySize, shmem);
    cudaFuncSetAttribute(mma_gemm<1>, cudaFuncAttributeMaxDynamicSharedMemorySize, shmem);
    cudaFuncSetAttribute(mma_gemm<2>, cudaFuncAttributeMaxDynamicSharedMemorySize, shmem);

    dim3 blk(256);
    dim3 gproj(MPROJ / 128, 4, 1);      // (1024, 4)
    mma_gemm<0><<<gproj, blk, shmem>>>(p_Hi, p_Wq, bq, nullptr, nullptr, nullptr, 0);
    mma_gemm<0><<<gproj, blk, shmem>>>(p_Hj, p_Wk, bk, nullptr, nullptr, nullptr, 1);
    mma_gemm<0><<<gproj, blk, shmem>>>(p_Hj, p_Wv, bv, nullptr, nullptr, nullptr, 2);

    transpose_v<<<dim3(16, 16, NHEADS), dim3(32, 8)>>>();

    dim3 ghead(4, 4, NHEADS);
    mma_gemm<1><<<ghead, blk, shmem>>>(nullptr, nullptr, nullptr, nullptr, lg, lt, 0);

    softmax_kernel<<<NHEADS * Tt, 128>>>();

    mma_gemm<2><<<ghead, blk, shmem>>>(nullptr, nullptr, nullptr, out, nullptr, nullptr, 0);
}

// round 5
// speedup vs baseline: 4.9333x; 2.1807x over previous
#include <cuda_runtime.h>
#include <cuda_fp16.h>
#include <cstdint>
#include <math.h>

constexpr int Tt = 512, NHc = 64, Dd = 512, Bb = 4;
constexpr int NHEADS = Bb * NHc;        // 256
constexpr int MPROJ  = Bb * Tt * NHc;   // 131072

// Scratch (device globals; no cudaMalloc allowed)
__device__ __half g_Hi[(size_t)MPROJ * Dd];
__device__ __half g_Hj[(size_t)MPROJ * Dd];
__device__ __half g_Wq[(size_t)Dd * Dd];
__device__ __half g_Wk[(size_t)Dd * Dd];
__device__ __half g_Wv[(size_t)Dd * Dd];
__device__ __half g_Q [(size_t)MPROJ * Dd];        // [B,T,N,D]
__device__ __half g_K [(size_t)MPROJ * Dd];        // [B,T,N,D]
__device__ __half g_V [(size_t)MPROJ * Dd];        // [B,T,N,D]
__device__ __half g_Vt[(size_t)NHEADS * Dd * Tt];  // [B,N,D,S]
__device__ float  g_S [(size_t)NHEADS * Tt * Tt];  // scores f32
__device__ __half g_Sh[(size_t)NHEADS * Tt * Tt];  // probs fp16

__device__ __forceinline__ uint32_t smem_u32(const void* p) {
    uint32_t a;
    asm("{ .reg .u64 t; cvta.to.shared.u64 t, %1; cvt.u32.u64 %0, t; }" : "=r"(a) : "l"(p));
    return a;
}
__device__ __forceinline__ void cp_async16(uint32_t saddr, const void* gptr) {
    asm volatile("cp.async.cg.shared.global [%0], [%1], 16;" :: "r"(saddr), "l"(gptr));
}
__device__ __forceinline__ void cp_commit() {
    asm volatile("cp.async.commit_group;" ::: "memory");
}
template<int N> __device__ __forceinline__ void cp_wait() {
    asm volatile("cp.async.wait_group %0;" :: "n"(N) : "memory");
}
__device__ __forceinline__ void ldsm_x4(uint32_t& r0, uint32_t& r1, uint32_t& r2, uint32_t& r3,
                                        uint32_t a) {
    asm volatile("ldmatrix.sync.aligned.m8n8.x4.shared.b16 {%0,%1,%2,%3}, [%4];"
                 : "=r"(r0), "=r"(r1), "=r"(r2), "=r"(r3) : "r"(a));
}
__device__ __forceinline__ void mma_f16(float& d0, float& d1, float& d2, float& d3,
                                        uint32_t a0, uint32_t a1, uint32_t a2, uint32_t a3,
                                        uint32_t b0, uint32_t b1) {
    asm volatile(
        "mma.sync.aligned.m16n8k16.row.col.f32.f16.f16.f32 "
        "{%0,%1,%2,%3}, {%4,%5,%6,%7}, {%8,%9}, {%0,%1,%2,%3};"
        : "+f"(d0), "+f"(d1), "+f"(d2), "+f"(d3)
        : "r"(a0), "r"(a1), "r"(a2), "r"(a3), "r"(b0), "r"(b1));
}

// ---------------- f32 -> f16 pre-pass ----------------
__global__ __launch_bounds__(256)
void to_half(const float* __restrict__ src, __half* __restrict__ dst, size_t n4)
{
    size_t i = (size_t)blockIdx.x * blockDim.x + threadIdx.x;
    size_t stride = (size_t)gridDim.x * blockDim.x;
    for (; i < n4; i += stride) {
        float4 v = ((const float4*)src)[i];
        __half2 h0 = __floats2half2_rn(v.x, v.y);
        __half2 h1 = __floats2half2_rn(v.z, v.w);
        uint2 u = { *(uint32_t*)&h0, *(uint32_t*)&h1 };
        ((uint2*)dst)[i] = u;
    }
}

// ---------------- fp16 mma.sync GEMM (cp.async + ldmatrix) ----------------
// All modes NT with k-contiguous rows:
// MODE 0: proj  C[m,n] = H[m,:]@W[n,:] + b[n]  -> g_Q/g_K/g_V (fp16 store)
// MODE 1: qk    S = scale*Q@K^T + decay_log    per head (rows strided 32768) -> g_S f32
// MODE 2: pv    O = P@Vt^T                     per head -> out[b,t,n,d] f32
// Tile 128x128, K=512 in 8 stages of BK=64 halfs (128B rows), double-buffered.
// smem: row stride 128B; 16B chunk c at swizzled slot c ^ (row & 7).
template<int MODE>
__global__ __launch_bounds__(256, 2)
void mma_gemm(const __half* __restrict__ Ag, const __half* __restrict__ Bg,
              const float* __restrict__ bias, float* __restrict__ Outg,
              const float* __restrict__ lg, const float* __restrict__ lt,
              int which)
{
    extern __shared__ __half sm[];   // [2 bufs][A:128x128B | B:128x128B] = 64KB
    const uint32_t smbase = smem_u32(sm);

    const int tid  = threadIdx.x;
    const int wid  = tid >> 5, lane = tid & 31;
    const int wm   = wid >> 2;          // 0..1
    const int wn   = wid & 3;           // 0..3
    const int m0   = blockIdx.x * 128;
    const int n0   = blockIdx.y * 128;
    const int h    = blockIdx.z;

    const __half *A, *B;
    size_t sA, sB;  // row strides in halfs
    if constexpr (MODE == 0) {
        A = Ag + (size_t)m0 * 512; sA = 512;
        B = Bg + (size_t)n0 * 512; sB = 512;
    } else if constexpr (MODE == 1) {
        int b = h >> 6, n = h & 63;
        size_t base = ((size_t)b * 32768 + (size_t)n) * 512;
        A = g_Q + base + (size_t)m0 * 32768; sA = 32768;
        B = g_K + base + (size_t)n0 * 32768; sB = 32768;
    } else {
        A = g_Sh + (size_t)h * (Tt * Tt) + (size_t)m0 * 512; sA = 512;
        B = g_Vt + (size_t)h * (Dd * Tt) + (size_t)n0 * 512; sB = 512;
    }

    // cp.async staging: thread -> row (tid>>1), 4 chunks at base (tid&1)*4
    const int srow = tid >> 1;
    const int cb0  = (tid & 1) * 4;
    const __half* agp = A + (size_t)srow * sA + cb0 * 8;
    const __half* bgp = B + (size_t)srow * sB + cb0 * 8;
    uint32_t swoff[4];
#pragma unroll
    for (int i = 0; i < 4; i++)
        swoff[i] = (uint32_t)srow * 128 + (uint32_t)(((cb0 + i) ^ (srow & 7)) << 4);

    auto issue = [&](int s) {
        uint32_t ab = smbase + (uint32_t)(s & 1) * 32768;
        uint32_t bb = ab + 16384;
        const __half* ag = agp + s * 64;
        const __half* bg = bgp + s * 64;
#pragma unroll
        for (int i = 0; i < 4; i++) {
            cp_async16(ab + swoff[i], ag + i * 8);
            cp_async16(bb + swoff[i], bg + i * 8);
        }
        cp_commit();
    };

    // ldmatrix address precompute
    const int mfrag = wm * 64, nfrag = wn * 32;
    const int aChunkLo = lane >> 4;            // 0/1
    const int bChunkLo = (lane >> 3) & 1;      // 0/1
    uint32_t aRowOff[4]; int aSw[4];
#pragma unroll
    for (int mt = 0; mt < 4; mt++) {
        int row = mfrag + mt * 16 + (lane & 15);
        aRowOff[mt] = (uint32_t)row * 128; aSw[mt] = row & 7;
    }
    uint32_t bRowOff[2]; int bSw[2];
#pragma unroll
    for (int ntp = 0; ntp < 2; ntp++) {
        int row = nfrag + ntp * 16 + (lane & 7) + ((lane >> 4) << 3);
        bRowOff[ntp] = (uint32_t)row * 128; bSw[ntp] = row & 7;
    }

    float acc[4][4][4];
#pragma unroll
    for (int mt = 0; mt < 4; mt++)
#pragma unroll
        for (int nt = 0; nt < 4; nt++)
#pragma unroll
            for (int e = 0; e < 4; e++) acc[mt][nt][e] = 0.f;

    issue(0);
    for (int s = 0; s < 8; s++) {
        if (s + 1 < 8) { issue(s + 1); cp_wait<1>(); }
        else           { cp_wait<0>(); }
        __syncthreads();

        uint32_t ab = smbase + (uint32_t)(s & 1) * 32768;
        uint32_t bb = ab + 16384;
#pragma unroll
        for (int ks = 0; ks < 4; ks++) {
            uint32_t afr[4][4], bfr[4][2];
#pragma unroll
            for (int mt = 0; mt < 4; mt++)
                ldsm_x4(afr[mt][0], afr[mt][1], afr[mt][2], afr[mt][3],
                        ab + aRowOff[mt] + (uint32_t)(((ks * 2 + aChunkLo) ^ aSw[mt]) << 4));
#pragma unroll
            for (int ntp = 0; ntp < 2; ntp++) {
                uint32_t r0, r1, r2, r3;
                ldsm_x4(r0, r1, r2, r3,
                        bb + bRowOff[ntp] + (uint32_t)(((ks * 2 + bChunkLo) ^ bSw[ntp]) << 4));
                bfr[2 * ntp][0] = r0; bfr[2 * ntp][1] = r1;
                bfr[2 * ntp + 1][0] = r2; bfr[2 * ntp + 1][1] = r3;
            }
#pragma unroll
            for (int mt = 0; mt < 4; mt++)
#pragma unroll
                for (int nt = 0; nt < 4; nt++)
                    mma_f16(acc[mt][nt][0], acc[mt][nt][1], acc[mt][nt][2], acc[mt][nt][3],
                            afr[mt][0], afr[mt][1], afr[mt][2], afr[mt][3],
                            bfr[nt][0], bfr[nt][1]);
        }
        __syncthreads();
    }

    // ---------------- epilogues ----------------
    // acc[mt][nt]: c0 -> (r, c), c1 -> (r, c+1), c2 -> (r+8, c), c3 -> (r+8, c+1)
    const int rq = lane >> 2, kq = lane & 3;
    if constexpr (MODE == 0) {
        __half* outp = (which == 0) ? g_Q : (which == 1) ? g_K : g_V;
#pragma unroll
        for (int mt = 0; mt < 4; mt++) {
            const int r = m0 + mfrag + mt * 16 + rq;
#pragma unroll
            for (int nt = 0; nt < 4; nt++) {
                const int c = n0 + nfrag + nt * 8 + kq * 2;
                float2 bv = *(const float2*)(bias + c);
                *(__half2*)(outp + (size_t)r * 512 + c) =
                    __floats2half2_rn(acc[mt][nt][0] + bv.x, acc[mt][nt][1] + bv.y);
                *(__half2*)(outp + (size_t)(r + 8) * 512 + c) =
                    __floats2half2_rn(acc[mt][nt][2] + bv.x, acc[mt][nt][3] + bv.y);
            }
        }
    } else if constexpr (MODE == 1) {
        const float gamma = fmaxf(__expf(*lg), 0.01f);
        const float tau   = fmaxf(__expf(*lt), 0.01f);
        const float scale = 1.0f / (22.62741699796952f * tau);
        float* Sh = g_S + (size_t)h * (Tt * Tt);
#pragma unroll
        for (int mt = 0; mt < 4; mt++) {
            const int r = m0 + mfrag + mt * 16 + rq;
#pragma unroll
            for (int nt = 0; nt < 4; nt++) {
                const int c = n0 + nfrag + nt * 8 + kq * 2;
#pragma unroll
                for (int half = 0; half < 2; half++) {
                    const int t = r + half * 8;
                    float2 v;
#pragma unroll
                    for (int e = 0; e < 2; e++) {
                        float gd = gamma * fabsf((float)(t - (c + e))) * (1.0f / 511.0f);
                        float dl = (gd < 11.0f) ? -gd : logf(expf(-gd) + 1e-8f);
                        ((float*)&v)[e] = acc[mt][nt][half * 2 + e] * scale + dl;
                    }
                    *(float2*)(Sh + (size_t)t * 512 + c) = v;
                }
            }
        }
    } else {
        const int b = h >> 6, n = h & 63;
#pragma unroll
        for (int mt = 0; mt < 4; mt++) {
            const int r = m0 + mfrag + mt * 16 + rq;
#pragma unroll
            for (int nt = 0; nt < 4; nt++) {
                const int c = n0 + nfrag + nt * 8 + kq * 2;
#pragma unroll
                for (int half = 0; half < 2; half++) {
                    const int t = r + half * 8;
                    float2 v = { acc[mt][nt][half * 2 + 0], acc[mt][nt][half * 2 + 1] };
                    *(float2*)(Outg + (((size_t)(b * Tt + t) * NHc + n) << 9) + c) = v;
                }
            }
        }
    }
}

// ---------------- V transpose: [B,S,N,D] (fp16) -> [(B,N),D,S] (fp16) ----------------
__global__ __launch_bounds__(256)
void transpose_v()
{
    __shared__ __half tile[32][40];
    const int h = blockIdx.z;
    const int b = h >> 6, n = h & 63;
    const int s0 = blockIdx.x * 32;
    const int d0 = blockIdx.y * 32;
    const __half* src = g_V + ((size_t)b * 32768 + (size_t)n) * 512;
#pragma unroll
    for (int i = threadIdx.y; i < 32; i += 8)
        tile[i][threadIdx.x] = src[(size_t)(s0 + i) * 32768 + d0 + threadIdx.x];
    __syncthreads();
    __half* dst = g_Vt + ((size_t)h * Dd + d0) * Tt + s0;
#pragma unroll
    for (int i = threadIdx.y; i < 32; i += 8)
        dst[(size_t)i * Tt + threadIdx.x] = tile[threadIdx.x][i];
}

// ---------------- Row softmax over Tj=512: f32 in, fp16 out ----------------
__global__ __launch_bounds__(128)
void softmax_kernel()
{
    __shared__ float red[8];
    size_t row = blockIdx.x;
    const float* p = g_S + row * 512;
    __half2* q = (__half2*)(g_Sh + row * 512);
    int tid = threadIdx.x;
    float4 v = *((const float4*)p + tid);
    float mx = fmaxf(fmaxf(v.x, v.y), fmaxf(v.z, v.w));
#pragma unroll
    for (int o = 16; o; o >>= 1) mx = fmaxf(mx, __shfl_xor_sync(0xffffffffu, mx, o));
    if ((tid & 31) == 0) red[tid >> 5] = mx;
    __syncthreads();
    mx = fmaxf(fmaxf(red[0], red[1]), fmaxf(red[2], red[3]));
    v.x = __expf(v.x - mx);
    v.y = __expf(v.y - mx);
    v.z = __expf(v.z - mx);
    v.w = __expf(v.w - mx);
    float s = v.x + v.y + v.z + v.w;
#pragma unroll
    for (int o = 16; o; o >>= 1) s += __shfl_xor_sync(0xffffffffu, s, o);
    if ((tid & 31) == 0) red[4 + (tid >> 5)] = s;
    __syncthreads();
    s = red[4] + red[5] + red[6] + red[7];
    float inv = 1.0f / s;
    q[tid * 2]     = __floats2half2_rn(v.x * inv, v.y * inv);
    q[tid * 2 + 1] = __floats2half2_rn(v.z * inv, v.w * inv);
}

extern "C" void kernel_launch(void* const* d_in, const int* in_sizes, int n_in,
                              void* d_out, int out_size)
{
    const float* H_i = (const float*)d_in[0];
    const float* H_j = (const float*)d_in[1];
    const float* Wq  = (const float*)d_in[2];
    const float* bq  = (const float*)d_in[3];
    const float* Wk  = (const float*)d_in[4];
    const float* bk  = (const float*)d_in[5];
    const float* Wv  = (const float*)d_in[6];
    const float* bv  = (const float*)d_in[7];
    const float* lg  = (const float*)d_in[8];
    const float* lt  = (const float*)d_in[9];
    float* out = (float*)d_out;

    __half *p_Hi, *p_Hj, *p_Wq, *p_Wk, *p_Wv;
    cudaGetSymbolAddress((void**)&p_Hi, g_Hi);
    cudaGetSymbolAddress((void**)&p_Hj, g_Hj);
    cudaGetSymbolAddress((void**)&p_Wq, g_Wq);
    cudaGetSymbolAddress((void**)&p_Wk, g_Wk);
    cudaGetSymbolAddress((void**)&p_Wv, g_Wv);

    to_half<<<8192, 256>>>(H_i, p_Hi, (size_t)MPROJ * Dd / 4);
    to_half<<<8192, 256>>>(H_j, p_Hj, (size_t)MPROJ * Dd / 4);
    to_half<<<256, 256>>>(Wq, p_Wq, (size_t)Dd * Dd / 4);
    to_half<<<256, 256>>>(Wk, p_Wk, (size_t)Dd * Dd / 4);
    to_half<<<256, 256>>>(Wv, p_Wv, (size_t)Dd * Dd / 4);

    const int shmem = 65536;  // 2 bufs x (16KB A + 16KB B)
    cudaFuncSetAttribute(mma_gemm<0>, cudaFuncAttributeMaxDynamicSharedMemorySize, shmem);
    cudaFuncSetAttribute(mma_gemm<1>, cudaFuncAttributeMaxDynamicSharedMemorySize, shmem);
    cudaFuncSetAttribute(mma_gemm<2>, cudaFuncAttributeMaxDynamicSharedMemorySize, shmem);

    dim3 blk(256);
    dim3 gproj(MPROJ / 128, 4, 1);      // (1024, 4)
    mma_gemm<0><<<gproj, blk, shmem>>>(p_Hi, p_Wq, bq, nullptr, nullptr, nullptr, 0);
    mma_gemm<0><<<gproj, blk, shmem>>>(p_Hj, p_Wk, bk, nullptr, nullptr, nullptr, 1);
    mma_gemm<0><<<gproj, blk, shmem>>>(p_Hj, p_Wv, bv, nullptr, nullptr, nullptr, 2);

    transpose_v<<<dim3(16, 16, NHEADS), dim3(32, 8)>>>();

    dim3 ghead(4, 4, NHEADS);
    mma_gemm<1><<<ghead, blk, shmem>>>(nullptr, nullptr, nullptr, nullptr, lg, lt, 0);

    softmax_kernel<<<NHEADS * Tt, 128>>>();

    mma_gemm<2><<<ghead, blk, shmem>>>(nullptr, nullptr, nullptr, out, nullptr, nullptr, 0);
}

// round 6
// speedup vs baseline: 5.2696x; 1.0682x over previous
#include <cuda_runtime.h>
#include <cuda_fp16.h>
#include <cstdint>
#include <math.h>

constexpr int Tt = 512, NHc = 64, Dd = 512, Bb = 4;
constexpr int NHEADS = Bb * NHc;        // 256
constexpr int MPROJ  = Bb * Tt * NHc;   // 131072

// Scratch (device globals; no cudaMalloc allowed)
__device__ __half g_Hi[(size_t)MPROJ * Dd];
__device__ __half g_Hj[(size_t)MPROJ * Dd];
__device__ __half g_Wq[(size_t)Dd * Dd];
__device__ __half g_Wk[(size_t)Dd * Dd];
__device__ __half g_Wv[(size_t)Dd * Dd];
__device__ __half g_Q [(size_t)MPROJ * Dd];        // [B,N,T,D] head-major
__device__ __half g_K [(size_t)MPROJ * Dd];        // [B,N,S,D] head-major
__device__ __half g_V [(size_t)MPROJ * Dd];        // [B,N,S,D] head-major
__device__ __half g_Vt[(size_t)NHEADS * Dd * Tt];  // [B,N,D,S]

__device__ __forceinline__ uint32_t smem_u32(const void* p) {
    uint32_t a;
    asm("{ .reg .u64 t; cvta.to.shared.u64 t, %1; cvt.u32.u64 %0, t; }" : "=r"(a) : "l"(p));
    return a;
}
__device__ __forceinline__ void cp_async16(uint32_t saddr, const void* gptr) {
    asm volatile("cp.async.cg.shared.global [%0], [%1], 16;" :: "r"(saddr), "l"(gptr));
}
__device__ __forceinline__ void cp_commit() {
    asm volatile("cp.async.commit_group;" ::: "memory");
}
template<int N> __device__ __forceinline__ void cp_wait() {
    asm volatile("cp.async.wait_group %0;" :: "n"(N) : "memory");
}
__device__ __forceinline__ void ldsm_x4(uint32_t& r0, uint32_t& r1, uint32_t& r2, uint32_t& r3,
                                        uint32_t a) {
    asm volatile("ldmatrix.sync.aligned.m8n8.x4.shared.b16 {%0,%1,%2,%3}, [%4];"
                 : "=r"(r0), "=r"(r1), "=r"(r2), "=r"(r3) : "r"(a));
}
__device__ __forceinline__ void mma_f16(float& d0, float& d1, float& d2, float& d3,
                                        uint32_t a0, uint32_t a1, uint32_t a2, uint32_t a3,
                                        uint32_t b0, uint32_t b1) {
    asm volatile(
        "mma.sync.aligned.m16n8k16.row.col.f32.f16.f16.f32 "
        "{%0,%1,%2,%3}, {%4,%5,%6,%7}, {%8,%9}, {%0,%1,%2,%3};"
        : "+f"(d0), "+f"(d1), "+f"(d2), "+f"(d3)
        : "r"(a0), "r"(a1), "r"(a2), "r"(a3), "r"(b0), "r"(b1));
}
__device__ __forceinline__ float decay_log(float gamma, int dt) {
    float gd = gamma * fabsf((float)dt) * (1.0f / 511.0f);
    return (gd < 11.0f) ? -gd : logf(expf(-gd) + 1e-8f);
}

// ---------------- f32 -> f16 pre-pass ----------------
__global__ __launch_bounds__(256)
void to_half(const float* __restrict__ src, __half* __restrict__ dst, size_t n4)
{
    size_t i = (size_t)blockIdx.x * blockDim.x + threadIdx.x;
    size_t stride = (size_t)gridDim.x * blockDim.x;
    for (; i < n4; i += stride) {
        float4 v = ((const float4*)src)[i];
        __half2 h0 = __floats2half2_rn(v.x, v.y);
        __half2 h1 = __floats2half2_rn(v.z, v.w);
        uint2 u = { *(uint32_t*)&h0, *(uint32_t*)&h1 };
        ((uint2*)dst)[i] = u;
    }
}

// ---------------- Projection GEMM (fp16 mma, head-major store) ----------------
// C[m,n] = H[m,:] @ W[n,:] + b[n], stored to g_Q/g_K/g_V as [B,N,T,D].
// Tile 128x128, K=512 in 8 stages of BK=64 (128B rows), cp.async double-buffered.
__global__ __launch_bounds__(256, 2)
void proj_gemm(const __half* __restrict__ Ag, const __half* __restrict__ Bg,
               const float* __restrict__ bias, int which)
{
    extern __shared__ __half sm[];   // [2 bufs][A 16KB | B 16KB] = 64KB
    const uint32_t smbase = smem_u32(sm);

    const int tid = threadIdx.x;
    const int wid = tid >> 5, lane = tid & 31;
    const int wm = wid >> 2, wn = wid & 3;
    const int m0 = blockIdx.x * 128;
    const int n0 = blockIdx.y * 128;

    const __half* A = Ag + (size_t)m0 * 512;
    const __half* B = Bg + (size_t)n0 * 512;

    const int srow = tid >> 1;
    const int cb0  = (tid & 1) * 4;
    const __half* agp = A + (size_t)srow * 512 + cb0 * 8;
    const __half* bgp = B + (size_t)srow * 512 + cb0 * 8;
    uint32_t swoff[4];
#pragma unroll
    for (int i = 0; i < 4; i++)
        swoff[i] = (uint32_t)srow * 128 + (uint32_t)(((cb0 + i) ^ (srow & 7)) << 4);

    auto issue = [&](int s) {
        uint32_t ab = smbase + (uint32_t)(s & 1) * 32768;
        uint32_t bb = ab + 16384;
        const __half* ag = agp + s * 64;
        const __half* bg = bgp + s * 64;
#pragma unroll
        for (int i = 0; i < 4; i++) {
            cp_async16(ab + swoff[i], ag + i * 8);
            cp_async16(bb + swoff[i], bg + i * 8);
        }
        cp_commit();
    };

    const int mfrag = wm * 64, nfrag = wn * 32;
    const int aChunkLo = lane >> 4;
    const int bChunkLo = (lane >> 3) & 1;
    uint32_t aRowOff[4]; int aSw[4];
#pragma unroll
    for (int mt = 0; mt < 4; mt++) {
        int row = mfrag + mt * 16 + (lane & 15);
        aRowOff[mt] = (uint32_t)row * 128; aSw[mt] = row & 7;
    }
    uint32_t bRowOff[2]; int bSw[2];
#pragma unroll
    for (int ntp = 0; ntp < 2; ntp++) {
        int row = nfrag + ntp * 16 + (lane & 7) + ((lane >> 4) << 3);
        bRowOff[ntp] = (uint32_t)row * 128; bSw[ntp] = row & 7;
    }

    float acc[4][4][4];
#pragma unroll
    for (int mt = 0; mt < 4; mt++)
#pragma unroll
        for (int nt = 0; nt < 4; nt++)
#pragma unroll
            for (int e = 0; e < 4; e++) acc[mt][nt][e] = 0.f;

    issue(0);
    for (int s = 0; s < 8; s++) {
        if (s + 1 < 8) { issue(s + 1); cp_wait<1>(); }
        else           { cp_wait<0>(); }
        __syncthreads();
        uint32_t ab = smbase + (uint32_t)(s & 1) * 32768;
        uint32_t bb = ab + 16384;
#pragma unroll
        for (int ks = 0; ks < 4; ks++) {
            uint32_t afr[4][4], bfr[4][2];
#pragma unroll
            for (int mt = 0; mt < 4; mt++)
                ldsm_x4(afr[mt][0], afr[mt][1], afr[mt][2], afr[mt][3],
                        ab + aRowOff[mt] + (uint32_t)(((ks * 2 + aChunkLo) ^ aSw[mt]) << 4));
#pragma unroll
            for (int ntp = 0; ntp < 2; ntp++) {
                uint32_t r0, r1, r2, r3;
                ldsm_x4(r0, r1, r2, r3,
                        bb + bRowOff[ntp] + (uint32_t)(((ks * 2 + bChunkLo) ^ bSw[ntp]) << 4));
                bfr[2 * ntp][0] = r0; bfr[2 * ntp][1] = r1;
                bfr[2 * ntp + 1][0] = r2; bfr[2 * ntp + 1][1] = r3;
            }
#pragma unroll
            for (int mt = 0; mt < 4; mt++)
#pragma unroll
                for (int nt = 0; nt < 4; nt++)
                    mma_f16(acc[mt][nt][0], acc[mt][nt][1], acc[mt][nt][2], acc[mt][nt][3],
                            afr[mt][0], afr[mt][1], afr[mt][2], afr[mt][3],
                            bfr[nt][0], bfr[nt][1]);
        }
        __syncthreads();
    }

    // epilogue: head-major store  m=((b*512+t)*64+n) -> dst ((b*64+n)*512+t)*512+c
    const int rq = lane >> 2, kq = lane & 3;
    __half* outp = (which == 0) ? g_Q : (which == 1) ? g_K : g_V;
#pragma unroll
    for (int mt = 0; mt < 4; mt++) {
        const int m = m0 + mfrag + mt * 16 + rq;
        const int b = m >> 15, t = (m >> 6) & 511, n = m & 63;
        __half* dst0 = outp + ((size_t)((b * NHc + n) * Tt + t)) * 512;
#pragma unroll
        for (int nt = 0; nt < 4; nt++) {
            const int c = n0 + nfrag + nt * 8 + kq * 2;
            float2 bv = *(const float2*)(bias + c);
            *(__half2*)(dst0 + c) =
                __floats2half2_rn(acc[mt][nt][0] + bv.x, acc[mt][nt][1] + bv.y);
        }
        const int m8 = m + 8;
        const int b8 = m8 >> 15, t8 = (m8 >> 6) & 511, n8 = m8 & 63;
        __half* dst8 = outp + ((size_t)((b8 * NHc + n8) * Tt + t8)) * 512;
#pragma unroll
        for (int nt = 0; nt < 4; nt++) {
            const int c = n0 + nfrag + nt * 8 + kq * 2;
            float2 bv = *(const float2*)(bias + c);
            *(__half2*)(dst8 + c) =
                __floats2half2_rn(acc[mt][nt][2] + bv.x, acc[mt][nt][3] + bv.y);
        }
    }
}

// ---------------- V transpose: [B,N,S,D] -> [B,N,D,S] ----------------
__global__ __launch_bounds__(256)
void transpose_v()
{
    __shared__ __half tile[32][40];
    const int h = blockIdx.z;
    const int s0 = blockIdx.x * 32;
    const int d0 = blockIdx.y * 32;
    const __half* src = g_V + (size_t)h * (Tt * Dd);
#pragma unroll
    for (int i = threadIdx.y; i < 32; i += 8)
        tile[i][threadIdx.x] = src[(size_t)(s0 + i) * 512 + d0 + threadIdx.x];
    __syncthreads();
    __half* dst = g_Vt + (size_t)h * (Dd * Tt) + (size_t)d0 * Tt + s0;
#pragma unroll
    for (int i = threadIdx.y; i < 32; i += 8)
        dst[(size_t)i * Tt + threadIdx.x] = tile[threadIdx.x][i];
}

// ---------------- Fused attention: S=QK^T+bias -> exp -> rowsum -> O=P@Vt^T ----------------
// Grid (4 Ti-tiles, 256 heads), 512 threads = 16 warps as 4(m)x4(n); warp tile 32x32.
// smem: P fp16 [128][512] swizzled (128KB) | 2 stage bufs (A 16KB + B 16KB each)
//       | rsum f32 [4][128] | invl f32 [128]
__global__ __launch_bounds__(512, 1)
void attn_fused(float* __restrict__ Outg,
                const float* __restrict__ lg, const float* __restrict__ lt)
{
    extern __shared__ __half sm[];
    float* rsum = (float*)(sm + 98304);   // 4*128
    float* invl = rsum + 512;             // 128
    const uint32_t smbase  = smem_u32(sm);
    const uint32_t pbase   = smbase;           // P: [0, 131072) bytes
    const uint32_t stgbase = smbase + 131072;  // stage bufs

    const int tid = threadIdx.x;
    const int wid = tid >> 5, lane = tid & 31;
    const int wm = wid >> 2, wn = wid & 3;
    const int mfrag = wm * 32, nfrag = wn * 32;
    const int rq = lane >> 2, kq = lane & 3;
    const int m0 = blockIdx.x * 128;
    const int h  = blockIdx.y;
    const int b  = h >> 6, n = h & 63;

    const __half* Qh = g_Q  + (size_t)h * (Tt * Dd) + (size_t)m0 * 512;
    const __half* Kh = g_K  + (size_t)h * (Tt * Dd);
    const __half* Vt = g_Vt + (size_t)h * (Dd * Tt);

    const float gamma = fmaxf(__expf(*lg), 0.01f);
    const float tau   = fmaxf(__expf(*lt), 0.01f);
    const float scale = 1.0f / (22.62741699796952f * tau);

    // cp.async staging: thread -> row tid>>2 (0..127), chunks (tid&3)*2, +1
    const int srow = tid >> 2;
    const int ch0  = (tid & 3) * 2;
    uint32_t sw[2];
#pragma unroll
    for (int i = 0; i < 2; i++)
        sw[i] = (uint32_t)srow * 128 + (uint32_t)(((ch0 + i) ^ (srow & 7)) << 4);

    // ldmatrix patterns (stage bufs: 128 rows x 128B)
    const int aChunkLo = lane >> 4;
    const int bChunkLo = (lane >> 3) & 1;
    uint32_t aRowOff[2]; int aSw[2];
#pragma unroll
    for (int mt = 0; mt < 2; mt++) {
        int row = mfrag + mt * 16 + (lane & 15);
        aRowOff[mt] = (uint32_t)row * 128; aSw[mt] = row & 7;
    }
    uint32_t bRowOff[2]; int bSw[2];
#pragma unroll
    for (int ntp = 0; ntp < 2; ntp++) {
        int row = nfrag + ntp * 16 + (lane & 7) + ((lane >> 4) << 3);
        bRowOff[ntp] = (uint32_t)row * 128; bSw[ntp] = row & 7;
    }
    // P (A-operand, phase 2): rows 128 x 1KB
    uint32_t pRowOff[2]; int pSw[2];
#pragma unroll
    for (int mt = 0; mt < 2; mt++) {
        int row = mfrag + mt * 16 + (lane & 15);
        pRowOff[mt] = (uint32_t)row * 1024; pSw[mt] = row & 7;
    }

    float rs[4] = {0.f, 0.f, 0.f, 0.f};   // row partial sums [mt*2 + half]

    // =============== Phase 1: P = exp(scale*QK^T + decay) ===============
    for (int jt = 0; jt < 4; jt++) {
        float acc[2][4][4];
#pragma unroll
        for (int mt = 0; mt < 2; mt++)
#pragma unroll
            for (int nt = 0; nt < 4; nt++)
#pragma unroll
                for (int e = 0; e < 4; e++) acc[mt][nt][e] = 0.f;

        const __half* Arow = Qh + (size_t)srow * 512 + ch0 * 8;
        const __half* Brow = Kh + (size_t)(jt * 128 + srow) * 512 + ch0 * 8;

        auto issue = [&](int s) {
            uint32_t ab = stgbase + (uint32_t)(s & 1) * 32768;
            uint32_t bb = ab + 16384;
#pragma unroll
            for (int i = 0; i < 2; i++) {
                cp_async16(ab + sw[i], Arow + s * 64 + i * 8);
                cp_async16(bb + sw[i], Brow + s * 64 + i * 8);
            }
            cp_commit();
        };

        issue(0);
        for (int s = 0; s < 8; s++) {
            if (s + 1 < 8) { issue(s + 1); cp_wait<1>(); }
            else           { cp_wait<0>(); }
            __syncthreads();
            uint32_t ab = stgbase + (uint32_t)(s & 1) * 32768;
            uint32_t bb = ab + 16384;
#pragma unroll
            for (int ks = 0; ks < 4; ks++) {
                uint32_t afr[2][4], bfr[4][2];
#pragma unroll
                for (int mt = 0; mt < 2; mt++)
                    ldsm_x4(afr[mt][0], afr[mt][1], afr[mt][2], afr[mt][3],
                            ab + aRowOff[mt] + (uint32_t)(((ks * 2 + aChunkLo) ^ aSw[mt]) << 4));
#pragma unroll
                for (int ntp = 0; ntp < 2; ntp++) {
                    uint32_t r0, r1, r2, r3;
                    ldsm_x4(r0, r1, r2, r3,
                            bb + bRowOff[ntp] + (uint32_t)(((ks * 2 + bChunkLo) ^ bSw[ntp]) << 4));
                    bfr[2 * ntp][0] = r0; bfr[2 * ntp][1] = r1;
                    bfr[2 * ntp + 1][0] = r2; bfr[2 * ntp + 1][1] = r3;
                }
#pragma unroll
                for (int mt = 0; mt < 2; mt++)
#pragma unroll
                    for (int nt = 0; nt < 4; nt++)
                        mma_f16(acc[mt][nt][0], acc[mt][nt][1], acc[mt][nt][2], acc[mt][nt][3],
                                afr[mt][0], afr[mt][1], afr[mt][2], afr[mt][3],
                                bfr[nt][0], bfr[nt][1]);
            }
            __syncthreads();
        }

        // bias + exp + store P + rowsum partials
#pragma unroll
        for (int mt = 0; mt < 2; mt++) {
            const int r  = mfrag + mt * 16 + rq;   // local tile row
            const int t0 = m0 + r, t1 = t0 + 8;
#pragma unroll
            for (int nt = 0; nt < 4; nt++) {
                const int c  = nfrag + nt * 8 + kq * 2;
                const int sg = jt * 128 + c;       // global s column
                float e00 = __expf(fmaf(acc[mt][nt][0], scale, decay_log(gamma, t0 - sg)));
                float e01 = __expf(fmaf(acc[mt][nt][1], scale, decay_log(gamma, t0 - sg - 1)));
                float e10 = __expf(fmaf(acc[mt][nt][2], scale, decay_log(gamma, t1 - sg)));
                float e11 = __expf(fmaf(acc[mt][nt][3], scale, decay_log(gamma, t1 - sg - 1)));
                uint32_t hoff0 = (uint32_t)r * 512 + (uint32_t)((((sg >> 3) ^ (r & 7)) << 3) + (sg & 7));
                uint32_t hoff1 = (uint32_t)(r + 8) * 512 + (uint32_t)((((sg >> 3) ^ ((r + 8) & 7)) << 3) + (sg & 7));
                *(__half2*)(sm + hoff0) = __floats2half2_rn(e00, e01);
                *(__half2*)(sm + hoff1) = __floats2half2_rn(e10, e11);
                rs[mt * 2 + 0] += e00 + e01;
                rs[mt * 2 + 1] += e10 + e11;
            }
        }
    }

    // rowsum reduce
#pragma unroll
    for (int i = 0; i < 4; i++) {
        rs[i] += __shfl_xor_sync(0xffffffffu, rs[i], 1);
        rs[i] += __shfl_xor_sync(0xffffffffu, rs[i], 2);
    }
    if (kq == 0) {
#pragma unroll
        for (int mt = 0; mt < 2; mt++) {
            const int r = mfrag + mt * 16 + rq;
            rsum[wn * 128 + r]     = rs[mt * 2 + 0];
            rsum[wn * 128 + r + 8] = rs[mt * 2 + 1];
        }
    }
    __syncthreads();
    if (tid < 128)
        invl[tid] = 1.0f / (rsum[tid] + rsum[128 + tid] + rsum[256 + tid] + rsum[384 + tid]);
    __syncthreads();

    // =============== Phase 2: O = P @ Vt^T, scaled by invl ===============
    for (int dc = 0; dc < 4; dc++) {
        float acc[2][4][4];
#pragma unroll
        for (int mt = 0; mt < 2; mt++)
#pragma unroll
            for (int nt = 0; nt < 4; nt++)
#pragma unroll
                for (int e = 0; e < 4; e++) acc[mt][nt][e] = 0.f;

        const __half* Vrow = Vt + (size_t)(dc * 128 + srow) * 512 + ch0 * 8;

        auto issueB = [&](int s) {
            uint32_t bb = stgbase + (uint32_t)(s & 1) * 32768 + 16384;
#pragma unroll
            for (int i = 0; i < 2; i++)
                cp_async16(bb + sw[i], Vrow + s * 64 + i * 8);
            cp_commit();
        };

        issueB(0);
        for (int s = 0; s < 8; s++) {
            if (s + 1 < 8) { issueB(s + 1); cp_wait<1>(); }
            else           { cp_wait<0>(); }
            __syncthreads();
            uint32_t bb = stgbase + (uint32_t)(s & 1) * 32768 + 16384;
#pragma unroll
            for (int ks = 0; ks < 4; ks++) {
                uint32_t afr[2][4], bfr[4][2];
#pragma unroll
                for (int mt = 0; mt < 2; mt++) {
                    uint32_t achunk = (uint32_t)(s * 8 + ks * 2 + aChunkLo);
                    ldsm_x4(afr[mt][0], afr[mt][1], afr[mt][2], afr[mt][3],
                            pbase + pRowOff[mt] + ((achunk ^ (uint32_t)pSw[mt]) << 4));
                }
#pragma unroll
                for (int ntp = 0; ntp < 2; ntp++) {
                    uint32_t r0, r1, r2, r3;
                    ldsm_x4(r0, r1, r2, r3,
                            bb + bRowOff[ntp] + (uint32_t)(((ks * 2 + bChunkLo) ^ bSw[ntp]) << 4));
                    bfr[2 * ntp][0] = r0; bfr[2 * ntp][1] = r1;
                    bfr[2 * ntp + 1][0] = r2; bfr[2 * ntp + 1][1] = r3;
                }
#pragma unroll
                for (int mt = 0; mt < 2; mt++)
#pragma unroll
                    for (int nt = 0; nt < 4; nt++)
                        mma_f16(acc[mt][nt][0], acc[mt][nt][1], acc[mt][nt][2], acc[mt][nt][3],
                                afr[mt][0], afr[mt][1], afr[mt][2], afr[mt][3],
                                bfr[nt][0], bfr[nt][1]);
            }
            __syncthreads();
        }

        // epilogue: scale by invl, store out[b,t,n,d]
#pragma unroll
        for (int mt = 0; mt < 2; mt++) {
            const int r = mfrag + mt * 16 + rq;
            const float il0 = invl[r], il1 = invl[r + 8];
            const int t0 = m0 + r;
            float* dst0 = Outg + (((size_t)(b * Tt + t0) * NHc + n) << 9);
            float* dst1 = Outg + (((size_t)(b * Tt + t0 + 8) * NHc + n) << 9);
#pragma unroll
            for (int nt = 0; nt < 4; nt++) {
                const int c = dc * 128 + nfrag + nt * 8 + kq * 2;
                float2 v0 = { acc[mt][nt][0] * il0, acc[mt][nt][1] * il0 };
                float2 v1 = { acc[mt][nt][2] * il1, acc[mt][nt][3] * il1 };
                *(float2*)(dst0 + c) = v0;
                *(float2*)(dst1 + c) = v1;
            }
        }
    }
}

extern "C" void kernel_launch(void* const* d_in, const int* in_sizes, int n_in,
                              void* d_out, int out_size)
{
    const float* H_i = (const float*)d_in[0];
    const float* H_j = (const float*)d_in[1];
    const float* Wq  = (const float*)d_in[2];
    const float* bq  = (const float*)d_in[3];
    const float* Wk  = (const float*)d_in[4];
    const float* bk  = (const float*)d_in[5];
    const float* Wv  = (const float*)d_in[6];
    const float* bv  = (const float*)d_in[7];
    const float* lg  = (const float*)d_in[8];
    const float* lt  = (const float*)d_in[9];
    float* out = (float*)d_out;

    __half *p_Hi, *p_Hj, *p_Wq, *p_Wk, *p_Wv;
    cudaGetSymbolAddress((void**)&p_Hi, g_Hi);
    cudaGetSymbolAddress((void**)&p_Hj, g_Hj);
    cudaGetSymbolAddress((void**)&p_Wq, g_Wq);
    cudaGetSymbolAddress((void**)&p_Wk, g_Wk);
    cudaGetSymbolAddress((void**)&p_Wv, g_Wv);

    to_half<<<8192, 256>>>(H_i, p_Hi, (size_t)MPROJ * Dd / 4);
    to_half<<<8192, 256>>>(H_j, p_Hj, (size_t)MPROJ * Dd / 4);
    to_half<<<256, 256>>>(Wq, p_Wq, (size_t)Dd * Dd / 4);
    to_half<<<256, 256>>>(Wk, p_Wk, (size_t)Dd * Dd / 4);
    to_half<<<256, 256>>>(Wv, p_Wv, (size_t)Dd * Dd / 4);

    const int proj_shmem = 65536;
    cudaFuncSetAttribute(proj_gemm, cudaFuncAttributeMaxDynamicSharedMemorySize, proj_shmem);

    dim3 blk(256);
    dim3 gproj(MPROJ / 128, 4, 1);
    proj_gemm<<<gproj, blk, proj_shmem>>>(p_Hi, p_Wq, bq, 0);
    proj_gemm<<<gproj, blk, proj_shmem>>>(p_Hj, p_Wk, bk, 1);
    proj_gemm<<<gproj, blk, proj_shmem>>>(p_Hj, p_Wv, bv, 2);

    transpose_v<<<dim3(16, 16, NHEADS), dim3(32, 8)>>>();

    // P 128KB + 2x32KB stage bufs + rsum/invl
    const int attn_shmem = 131072 + 65536 + 4 * (512 + 128);
    cudaFuncSetAttribute(attn_fused, cudaFuncAttributeMaxDynamicSharedMemorySize, attn_shmem);
    attn_fused<<<dim3(4, NHEADS), 512, attn_shmem>>>(out, lg, lt);
}

// round 7
// speedup vs baseline: 5.4416x; 1.0326x over previous
#include <cuda_runtime.h>
#include <cuda_fp16.h>
#include <cstdint>
#include <math.h>

constexpr int Tt = 512, NHc = 64, Dd = 512, Bb = 4;
constexpr int NHEADS = Bb * NHc;        // 256
constexpr int MPROJ  = Bb * Tt * NHc;   // 131072

// Scratch (device globals; no cudaMalloc allowed)
__device__ __half g_Hi[(size_t)MPROJ * Dd];
__device__ __half g_Hj[(size_t)MPROJ * Dd];
__device__ __half g_Wq[(size_t)Dd * Dd];
__device__ __half g_Wk[(size_t)Dd * Dd];
__device__ __half g_Wv[(size_t)Dd * Dd];
__device__ __half g_Q [(size_t)MPROJ * Dd];        // [B,N,T,D] head-major
__device__ __half g_K [(size_t)MPROJ * Dd];        // [B,N,S,D] head-major
__device__ __half g_V [(size_t)MPROJ * Dd];        // [B,N,S,D] head-major
__device__ __half g_Vt[(size_t)NHEADS * Dd * Tt];  // [B,N,D,S]

__device__ __forceinline__ uint32_t smem_u32(const void* p) {
    uint32_t a;
    asm("{ .reg .u64 t; cvta.to.shared.u64 t, %1; cvt.u32.u64 %0, t; }" : "=r"(a) : "l"(p));
    return a;
}
__device__ __forceinline__ void cp_async16(uint32_t saddr, const void* gptr) {
    asm volatile("cp.async.cg.shared.global [%0], [%1], 16;" :: "r"(saddr), "l"(gptr));
}
__device__ __forceinline__ void cp_commit() {
    asm volatile("cp.async.commit_group;" ::: "memory");
}
template<int N> __device__ __forceinline__ void cp_wait() {
    asm volatile("cp.async.wait_group %0;" :: "n"(N) : "memory");
}
__device__ __forceinline__ void ldsm_x4(uint32_t& r0, uint32_t& r1, uint32_t& r2, uint32_t& r3,
                                        uint32_t a) {
    asm volatile("ldmatrix.sync.aligned.m8n8.x4.shared.b16 {%0,%1,%2,%3}, [%4];"
                 : "=r"(r0), "=r"(r1), "=r"(r2), "=r"(r3) : "r"(a));
}
__device__ __forceinline__ void mma_f16(float& d0, float& d1, float& d2, float& d3,
                                        uint32_t a0, uint32_t a1, uint32_t a2, uint32_t a3,
                                        uint32_t b0, uint32_t b1) {
    asm volatile(
        "mma.sync.aligned.m16n8k16.row.col.f32.f16.f16.f32 "
        "{%0,%1,%2,%3}, {%4,%5,%6,%7}, {%8,%9}, {%0,%1,%2,%3};"
        : "+f"(d0), "+f"(d1), "+f"(d2), "+f"(d3)
        : "r"(a0), "r"(a1), "r"(a2), "r"(a3), "r"(b0), "r"(b1));
}
__device__ __forceinline__ float decay_log(float gamma, int dt) {
    float gd = gamma * fabsf((float)dt) * (1.0f / 511.0f);
    return (gd < 11.0f) ? -gd : logf(expf(-gd) + 1e-8f);
}

// ---------------- f32 -> f16 pre-pass ----------------
__global__ __launch_bounds__(256)
void to_half(const float* __restrict__ src, __half* __restrict__ dst, size_t n4)
{
    size_t i = (size_t)blockIdx.x * blockDim.x + threadIdx.x;
    size_t stride = (size_t)gridDim.x * blockDim.x;
    for (; i < n4; i += stride) {
        float4 v = ((const float4*)src)[i];
        __half2 h0 = __floats2half2_rn(v.x, v.y);
        __half2 h1 = __floats2half2_rn(v.z, v.w);
        uint2 u = { *(uint32_t*)&h0, *(uint32_t*)&h1 };
        ((uint2*)dst)[i] = u;
    }
}

// ---------------- Projection GEMM (fp16 mma, head-major store) ----------------
// Grid (n-tiles=4, m-tiles=1024): adjacent bids share the A tile via L2.
// 3-stage cp.async ring, one __syncthreads per stage.
__global__ __launch_bounds__(256, 2)
void proj_gemm(const __half* __restrict__ Ag, const __half* __restrict__ Bg,
               const float* __restrict__ bias, int which)
{
    extern __shared__ __half sm[];   // 3 bufs x (A 16KB | B 16KB) = 96KB
    const uint32_t smbase = smem_u32(sm);

    const int tid = threadIdx.x;
    const int wid = tid >> 5, lane = tid & 31;
    const int wm = wid >> 2, wn = wid & 3;
    const int m0 = blockIdx.y * 128;
    const int n0 = blockIdx.x * 128;

    const __half* A = Ag + (size_t)m0 * 512;
    const __half* B = Bg + (size_t)n0 * 512;

    const int srow = tid >> 1;
    const int cb0  = (tid & 1) * 4;
    const __half* agp = A + (size_t)srow * 512 + cb0 * 8;
    const __half* bgp = B + (size_t)srow * 512 + cb0 * 8;
    uint32_t swoff[4];
#pragma unroll
    for (int i = 0; i < 4; i++)
        swoff[i] = (uint32_t)srow * 128 + (uint32_t)(((cb0 + i) ^ (srow & 7)) << 4);

    auto issue = [&](int s) {
        uint32_t ab = smbase + (uint32_t)(s % 3) * 32768;
        uint32_t bb = ab + 16384;
        const __half* ag = agp + s * 64;
        const __half* bg = bgp + s * 64;
#pragma unroll
        for (int i = 0; i < 4; i++) {
            cp_async16(ab + swoff[i], ag + i * 8);
            cp_async16(bb + swoff[i], bg + i * 8);
        }
        cp_commit();
    };

    const int mfrag = wm * 64, nfrag = wn * 32;
    const int aChunkLo = lane >> 4;
    const int bChunkLo = (lane >> 3) & 1;
    uint32_t aRowOff[4]; int aSw[4];
#pragma unroll
    for (int mt = 0; mt < 4; mt++) {
        int row = mfrag + mt * 16 + (lane & 15);
        aRowOff[mt] = (uint32_t)row * 128; aSw[mt] = row & 7;
    }
    uint32_t bRowOff[2]; int bSw[2];
#pragma unroll
    for (int ntp = 0; ntp < 2; ntp++) {
        int row = nfrag + ntp * 16 + (lane & 7) + ((lane >> 4) << 3);
        bRowOff[ntp] = (uint32_t)row * 128; bSw[ntp] = row & 7;
    }

    float acc[4][4][4];
#pragma unroll
    for (int mt = 0; mt < 4; mt++)
#pragma unroll
        for (int nt = 0; nt < 4; nt++)
#pragma unroll
            for (int e = 0; e < 4; e++) acc[mt][nt][e] = 0.f;

    issue(0); issue(1);
#pragma unroll 1
    for (int s = 0; s < 8; s++) {
        if (s < 7) cp_wait<1>(); else cp_wait<0>();
        __syncthreads();
        uint32_t ab = smbase + (uint32_t)(s % 3) * 32768;
        uint32_t bb = ab + 16384;
#pragma unroll
        for (int ks = 0; ks < 4; ks++) {
            uint32_t afr[4][4], bfr[4][2];
#pragma unroll
            for (int mt = 0; mt < 4; mt++)
                ldsm_x4(afr[mt][0], afr[mt][1], afr[mt][2], afr[mt][3],
                        ab + aRowOff[mt] + (uint32_t)(((ks * 2 + aChunkLo) ^ aSw[mt]) << 4));
#pragma unroll
            for (int ntp = 0; ntp < 2; ntp++) {
                uint32_t r0, r1, r2, r3;
                ldsm_x4(r0, r1, r2, r3,
                        bb + bRowOff[ntp] + (uint32_t)(((ks * 2 + bChunkLo) ^ bSw[ntp]) << 4));
                bfr[2 * ntp][0] = r0; bfr[2 * ntp][1] = r1;
                bfr[2 * ntp + 1][0] = r2; bfr[2 * ntp + 1][1] = r3;
            }
#pragma unroll
            for (int mt = 0; mt < 4; mt++)
#pragma unroll
                for (int nt = 0; nt < 4; nt++)
                    mma_f16(acc[mt][nt][0], acc[mt][nt][1], acc[mt][nt][2], acc[mt][nt][3],
                            afr[mt][0], afr[mt][1], afr[mt][2], afr[mt][3],
                            bfr[nt][0], bfr[nt][1]);
        }
        if (s + 2 < 8) issue(s + 2);
    }

    // epilogue: head-major store  m=((b*512+t)*64+n) -> dst ((b*64+n)*512+t)*512+c
    const int rq = lane >> 2, kq = lane & 3;
    __half* outp = (which == 0) ? g_Q : (which == 1) ? g_K : g_V;
#pragma unroll
    for (int mt = 0; mt < 4; mt++) {
        const int m = m0 + mfrag + mt * 16 + rq;
        const int b = m >> 15, t = (m >> 6) & 511, n = m & 63;
        __half* dst0 = outp + ((size_t)((b * NHc + n) * Tt + t)) * 512;
#pragma unroll
        for (int nt = 0; nt < 4; nt++) {
            const int c = n0 + nfrag + nt * 8 + kq * 2;
            float2 bv = *(const float2*)(bias + c);
            *(__half2*)(dst0 + c) =
                __floats2half2_rn(acc[mt][nt][0] + bv.x, acc[mt][nt][1] + bv.y);
        }
        const int m8 = m + 8;
        const int b8 = m8 >> 15, t8 = (m8 >> 6) & 511, n8 = m8 & 63;
        __half* dst8 = outp + ((size_t)((b8 * NHc + n8) * Tt + t8)) * 512;
#pragma unroll
        for (int nt = 0; nt < 4; nt++) {
            const int c = n0 + nfrag + nt * 8 + kq * 2;
            float2 bv = *(const float2*)(bias + c);
            *(__half2*)(dst8 + c) =
                __floats2half2_rn(acc[mt][nt][2] + bv.x, acc[mt][nt][3] + bv.y);
        }
    }
}

// ---------------- V transpose: [B,N,S,D] -> [B,N,D,S] ----------------
__global__ __launch_bounds__(256)
void transpose_v()
{
    __shared__ __half tile[32][40];
    const int h = blockIdx.z;
    const int s0 = blockIdx.x * 32;
    const int d0 = blockIdx.y * 32;
    const __half* src = g_V + (size_t)h * (Tt * Dd);
#pragma unroll
    for (int i = threadIdx.y; i < 32; i += 8)
        tile[i][threadIdx.x] = src[(size_t)(s0 + i) * 512 + d0 + threadIdx.x];
    __syncthreads();
    __half* dst = g_Vt + (size_t)h * (Dd * Tt) + (size_t)d0 * Tt + s0;
#pragma unroll
    for (int i = threadIdx.y; i < 32; i += 8)
        dst[(size_t)i * Tt + threadIdx.x] = tile[threadIdx.x][i];
}

// ---------------- Fused attention ----------------
// Grid (4 Ti-tiles, 256 heads), 512 threads = 16 warps as 4(m)x4(n).
// smem: P fp16 [128][512] swizzled (128KB) | 3 stage bufs (A 16KB + B 16KB)
//       | rsum f32 [4][128] | invl f32 [128]   -> 231936 B total
// Both phases run a FLAT 32-stage cp.async ring (no drain at tile boundaries).
__global__ __launch_bounds__(512, 1)
void attn_fused(float* __restrict__ Outg,
                const float* __restrict__ lg, const float* __restrict__ lt)
{
    extern __shared__ __half sm[];
    float* rsum = (float*)(sm + 114688);  // after P(128KB)+stages(96KB)
    float* invl = rsum + 512;
    const uint32_t smbase  = smem_u32(sm);
    const uint32_t pbase   = smbase;           // P: [0, 131072)
    const uint32_t stgbase = smbase + 131072;  // 3 x 32KB

    const int tid = threadIdx.x;
    const int wid = tid >> 5, lane = tid & 31;
    const int wm = wid >> 2, wn = wid & 3;
    const int mfrag = wm * 32, nfrag = wn * 32;
    const int rq = lane >> 2, kq = lane & 3;
    const int m0 = blockIdx.x * 128;
    const int h  = blockIdx.y;
    const int b  = h >> 6, n = h & 63;

    const __half* Qh = g_Q  + (size_t)h * (Tt * Dd) + (size_t)m0 * 512;
    const __half* Kh = g_K  + (size_t)h * (Tt * Dd);
    const __half* Vt = g_Vt + (size_t)h * (Dd * Tt);

    const float gamma = fmaxf(__expf(*lg), 0.01f);
    const float tau   = fmaxf(__expf(*lt), 0.01f);
    const float scale = 1.0f / (22.62741699796952f * tau);

    // staging: thread -> row tid>>2 (0..127), chunks (tid&3)*2, +1
    const int srow = tid >> 2;
    const int ch0  = (tid & 3) * 2;
    uint32_t sw[2];
#pragma unroll
    for (int i = 0; i < 2; i++)
        sw[i] = (uint32_t)srow * 128 + (uint32_t)(((ch0 + i) ^ (srow & 7)) << 4);

    const int aChunkLo = lane >> 4;
    const int bChunkLo = (lane >> 3) & 1;
    uint32_t aRowOff[2]; int aSw[2];
#pragma unroll
    for (int mt = 0; mt < 2; mt++) {
        int row = mfrag + mt * 16 + (lane & 15);
        aRowOff[mt] = (uint32_t)row * 128; aSw[mt] = row & 7;
    }
    uint32_t bRowOff[2]; int bSw[2];
#pragma unroll
    for (int ntp = 0; ntp < 2; ntp++) {
        int row = nfrag + ntp * 16 + (lane & 7) + ((lane >> 4) << 3);
        bRowOff[ntp] = (uint32_t)row * 128; bSw[ntp] = row & 7;
    }
    uint32_t pRowOff[2]; int pSw[2];
#pragma unroll
    for (int mt = 0; mt < 2; mt++) {
        int row = mfrag + mt * 16 + (lane & 15);
        pRowOff[mt] = (uint32_t)row * 1024; pSw[mt] = row & 7;
    }

    float rs[4] = {0.f, 0.f, 0.f, 0.f};
    const __half* Arow = Qh + (size_t)srow * 512 + ch0 * 8;

    // =============== Phase 1: flat 32 stages (4 jt x 8 k-stages) ===============
    auto issue1 = [&](int s) {
        const int jt = s >> 3, sk = s & 7;
        uint32_t ab = stgbase + (uint32_t)(s % 3) * 32768;
        uint32_t bb = ab + 16384;
        const __half* ag = Arow + sk * 64;
        const __half* bg = Kh + (size_t)(jt * 128 + srow) * 512 + ch0 * 8 + sk * 64;
#pragma unroll
        for (int i = 0; i < 2; i++) {
            cp_async16(ab + sw[i], ag + i * 8);
            cp_async16(bb + sw[i], bg + i * 8);
        }
        cp_commit();
    };

    float acc[2][4][4];
#pragma unroll
    for (int mt = 0; mt < 2; mt++)
#pragma unroll
        for (int nt = 0; nt < 4; nt++)
#pragma unroll
            for (int e = 0; e < 4; e++) acc[mt][nt][e] = 0.f;

    issue1(0); issue1(1);
#pragma unroll 1
    for (int s = 0; s < 32; s++) {
        if (s < 31) cp_wait<1>(); else cp_wait<0>();
        __syncthreads();
        uint32_t ab = stgbase + (uint32_t)(s % 3) * 32768;
        uint32_t bb = ab + 16384;
#pragma unroll
        for (int ks = 0; ks < 4; ks++) {
            uint32_t afr[2][4], bfr[4][2];
#pragma unroll
            for (int mt = 0; mt < 2; mt++)
                ldsm_x4(afr[mt][0], afr[mt][1], afr[mt][2], afr[mt][3],
                        ab + aRowOff[mt] + (uint32_t)(((ks * 2 + aChunkLo) ^ aSw[mt]) << 4));
#pragma unroll
            for (int ntp = 0; ntp < 2; ntp++) {
                uint32_t r0, r1, r2, r3;
                ldsm_x4(r0, r1, r2, r3,
                        bb + bRowOff[ntp] + (uint32_t)(((ks * 2 + bChunkLo) ^ bSw[ntp]) << 4));
                bfr[2 * ntp][0] = r0; bfr[2 * ntp][1] = r1;
                bfr[2 * ntp + 1][0] = r2; bfr[2 * ntp + 1][1] = r3;
            }
#pragma unroll
            for (int mt = 0; mt < 2; mt++)
#pragma unroll
                for (int nt = 0; nt < 4; nt++)
                    mma_f16(acc[mt][nt][0], acc[mt][nt][1], acc[mt][nt][2], acc[mt][nt][3],
                            afr[mt][0], afr[mt][1], afr[mt][2], afr[mt][3],
                            bfr[nt][0], bfr[nt][1]);
        }
        if (s + 2 < 32) issue1(s + 2);

        if ((s & 7) == 7) {
            // jt tile complete: bias + exp + store P + rowsum, reset acc
            const int jt = s >> 3;
#pragma unroll
            for (int mt = 0; mt < 2; mt++) {
                const int r  = mfrag + mt * 16 + rq;
                const int t0 = m0 + r, t1 = t0 + 8;
#pragma unroll
                for (int nt = 0; nt < 4; nt++) {
                    const int c  = nfrag + nt * 8 + kq * 2;
                    const int sg = jt * 128 + c;
                    float e00 = __expf(fmaf(acc[mt][nt][0], scale, decay_log(gamma, t0 - sg)));
                    float e01 = __expf(fmaf(acc[mt][nt][1], scale, decay_log(gamma, t0 - sg - 1)));
                    float e10 = __expf(fmaf(acc[mt][nt][2], scale, decay_log(gamma, t1 - sg)));
                    float e11 = __expf(fmaf(acc[mt][nt][3], scale, decay_log(gamma, t1 - sg - 1)));
                    uint32_t hoff0 = (uint32_t)r * 512 + (uint32_t)((((sg >> 3) ^ (r & 7)) << 3) + (sg & 7));
                    uint32_t hoff1 = (uint32_t)(r + 8) * 512 + (uint32_t)((((sg >> 3) ^ ((r + 8) & 7)) << 3) + (sg & 7));
                    *(__half2*)(sm + hoff0) = __floats2half2_rn(e00, e01);
                    *(__half2*)(sm + hoff1) = __floats2half2_rn(e10, e11);
                    rs[mt * 2 + 0] += e00 + e01;
                    rs[mt * 2 + 1] += e10 + e11;
                    acc[mt][nt][0] = 0.f; acc[mt][nt][1] = 0.f;
                    acc[mt][nt][2] = 0.f; acc[mt][nt][3] = 0.f;
                }
            }
        }
    }

    // rowsum reduce
#pragma unroll
    for (int i = 0; i < 4; i++) {
        rs[i] += __shfl_xor_sync(0xffffffffu, rs[i], 1);
        rs[i] += __shfl_xor_sync(0xffffffffu, rs[i], 2);
    }
    if (kq == 0) {
#pragma unroll
        for (int mt = 0; mt < 2; mt++) {
            const int r = mfrag + mt * 16 + rq;
            rsum[wn * 128 + r]     = rs[mt * 2 + 0];
            rsum[wn * 128 + r + 8] = rs[mt * 2 + 1];
        }
    }
    __syncthreads();
    if (tid < 128)
        invl[tid] = 1.0f / (rsum[tid] + rsum[128 + tid] + rsum[256 + tid] + rsum[384 + tid]);
    __syncthreads();

    // =============== Phase 2: flat 32 stages (4 dc x 8 k-stages) ===============
    auto issue2 = [&](int s) {
        const int dc = s >> 3, sk = s & 7;
        uint32_t bb = stgbase + (uint32_t)(s % 3) * 32768 + 16384;
        const __half* bg = Vt + (size_t)(dc * 128 + srow) * 512 + ch0 * 8 + sk * 64;
#pragma unroll
        for (int i = 0; i < 2; i++)
            cp_async16(bb + sw[i], bg + i * 8);
        cp_commit();
    };

    issue2(0); issue2(1);
#pragma unroll 1
    for (int s = 0; s < 32; s++) {
        if (s < 31) cp_wait<1>(); else cp_wait<0>();
        __syncthreads();
        const int sk = s & 7;
        uint32_t bb = stgbase + (uint32_t)(s % 3) * 32768 + 16384;
#pragma unroll
        for (int ks = 0; ks < 4; ks++) {
            uint32_t afr[2][4], bfr[4][2];
#pragma unroll
            for (int mt = 0; mt < 2; mt++) {
                uint32_t achunk = (uint32_t)(sk * 8 + ks * 2 + aChunkLo);
                ldsm_x4(afr[mt][0], afr[mt][1], afr[mt][2], afr[mt][3],
                        pbase + pRowOff[mt] + ((achunk ^ (uint32_t)pSw[mt]) << 4));
            }
#pragma unroll
            for (int ntp = 0; ntp < 2; ntp++) {
                uint32_t r0, r1, r2, r3;
                ldsm_x4(r0, r1, r2, r3,
                        bb + bRowOff[ntp] + (uint32_t)(((ks * 2 + bChunkLo) ^ bSw[ntp]) << 4));
                bfr[2 * ntp][0] = r0; bfr[2 * ntp][1] = r1;
                bfr[2 * ntp + 1][0] = r2; bfr[2 * ntp + 1][1] = r3;
            }
#pragma unroll
            for (int mt = 0; mt < 2; mt++)
#pragma unroll
                for (int nt = 0; nt < 4; nt++)
                    mma_f16(acc[mt][nt][0], acc[mt][nt][1], acc[mt][nt][2], acc[mt][nt][3],
                            afr[mt][0], afr[mt][1], afr[mt][2], afr[mt][3],
                            bfr[nt][0], bfr[nt][1]);
        }
        if (s + 2 < 32) issue2(s + 2);

        if ((s & 7) == 7) {
            const int dc = s >> 3;
#pragma unroll
            for (int mt = 0; mt < 2; mt++) {
                const int r = mfrag + mt * 16 + rq;
                const float il0 = invl[r], il1 = invl[r + 8];
                const int t0 = m0 + r;
                float* dst0 = Outg + (((size_t)(b * Tt + t0) * NHc + n) << 9);
                float* dst1 = Outg + (((size_t)(b * Tt + t0 + 8) * NHc + n) << 9);
#pragma unroll
                for (int nt = 0; nt < 4; nt++) {
                    const int c = dc * 128 + nfrag + nt * 8 + kq * 2;
                    float2 v0 = { acc[mt][nt][0] * il0, acc[mt][nt][1] * il0 };
                    float2 v1 = { acc[mt][nt][2] * il1, acc[mt][nt][3] * il1 };
                    *(float2*)(dst0 + c) = v0;
                    *(float2*)(dst1 + c) = v1;
                    acc[mt][nt][0] = 0.f; acc[mt][nt][1] = 0.f;
                    acc[mt][nt][2] = 0.f; acc[mt][nt][3] = 0.f;
                }
            }
        }
    }
}

extern "C" void kernel_launch(void* const* d_in, const int* in_sizes, int n_in,
                              void* d_out, int out_size)
{
    const float* H_i = (const float*)d_in[0];
    const float* H_j = (const float*)d_in[1];
    const float* Wq  = (const float*)d_in[2];
    const float* bq  = (const float*)d_in[3];
    const float* Wk  = (const float*)d_in[4];
    const float* bk  = (const float*)d_in[5];
    const float* Wv  = (const float*)d_in[6];
    const float* bv  = (const float*)d_in[7];
    const float* lg  = (const float*)d_in[8];
    const float* lt  = (const float*)d_in[9];
    float* out = (float*)d_out;

    __half *p_Hi, *p_Hj, *p_Wq, *p_Wk, *p_Wv;
    cudaGetSymbolAddress((void**)&p_Hi, g_Hi);
    cudaGetSymbolAddress((void**)&p_Hj, g_Hj);
    cudaGetSymbolAddress((void**)&p_Wq, g_Wq);
    cudaGetSymbolAddress((void**)&p_Wk, g_Wk);
    cudaGetSymbolAddress((void**)&p_Wv, g_Wv);

    to_half<<<8192, 256>>>(H_i, p_Hi, (size_t)MPROJ * Dd / 4);
    to_half<<<8192, 256>>>(H_j, p_Hj, (size_t)MPROJ * Dd / 4);
    to_half<<<256, 256>>>(Wq, p_Wq, (size_t)Dd * Dd / 4);
    to_half<<<256, 256>>>(Wk, p_Wk, (size_t)Dd * Dd / 4);
    to_half<<<256, 256>>>(Wv, p_Wv, (size_t)Dd * Dd / 4);

    const int proj_shmem = 3 * 32768;  // 96KB
    cudaFuncSetAttribute(proj_gemm, cudaFuncAttributeMaxDynamicSharedMemorySize, proj_shmem);

    dim3 blk(256);
    dim3 gproj(4, MPROJ / 128, 1);     // x = n-tile (L2-shared A), y = m-tile
    proj_gemm<<<gproj, blk, proj_shmem>>>(p_Hi, p_Wq, bq, 0);
    proj_gemm<<<gproj, blk, proj_shmem>>>(p_Hj, p_Wk, bk, 1);
    proj_gemm<<<gproj, blk, proj_shmem>>>(p_Hj, p_Wv, bv, 2);

    transpose_v<<<dim3(16, 16, NHEADS), dim3(32, 8)>>>();

    // P 128KB + 3x32KB stages + rsum(2KB) + invl(512B) = 231936 B
    const int attn_shmem = 131072 + 98304 + 2048 + 512;
    cudaFuncSetAttribute(attn_fused, cudaFuncAttributeMaxDynamicSharedMemorySize, attn_shmem);
    attn_fused<<<dim3(4, NHEADS), 512, attn_shmem>>>(out, lg, lt);
}

// round 8
// speedup vs baseline: 5.9907x; 1.1009x over previous
#include <cuda_runtime.h>
#include <cuda_fp16.h>
#include <cstdint>
#include <math.h>

constexpr int Tt = 512, NHc = 64, Dd = 512, Bb = 4;
constexpr int NHEADS = Bb * NHc;        // 256
constexpr int MPROJ  = Bb * Tt * NHc;   // 131072

// Scratch (device globals; no cudaMalloc allowed)
__device__ __half g_Hi[(size_t)MPROJ * Dd];
__device__ __half g_Hj[(size_t)MPROJ * Dd];
__device__ __half g_Wq[(size_t)Dd * Dd];
__device__ __half g_Wk[(size_t)Dd * Dd];
__device__ __half g_Wv[(size_t)Dd * Dd];
__device__ __half g_Q [(size_t)MPROJ * Dd];        // [B,N,T,D] head-major
__device__ __half g_K [(size_t)MPROJ * Dd];        // [B,N,S,D] head-major
__device__ __half g_V [(size_t)MPROJ * Dd];        // [B,N,S,D] head-major

__device__ __forceinline__ uint32_t smem_u32(const void* p) {
    uint32_t a;
    asm("{ .reg .u64 t; cvta.to.shared.u64 t, %1; cvt.u32.u64 %0, t; }" : "=r"(a) : "l"(p));
    return a;
}
__device__ __forceinline__ void cp_async16(uint32_t saddr, const void* gptr) {
    asm volatile("cp.async.cg.shared.global [%0], [%1], 16;" :: "r"(saddr), "l"(gptr));
}
__device__ __forceinline__ void cp_commit() {
    asm volatile("cp.async.commit_group;" ::: "memory");
}
template<int N> __device__ __forceinline__ void cp_wait() {
    asm volatile("cp.async.wait_group %0;" :: "n"(N) : "memory");
}
__device__ __forceinline__ void ldsm_x4(uint32_t& r0, uint32_t& r1, uint32_t& r2, uint32_t& r3,
                                        uint32_t a) {
    asm volatile("ldmatrix.sync.aligned.m8n8.x4.shared.b16 {%0,%1,%2,%3}, [%4];"
                 : "=r"(r0), "=r"(r1), "=r"(r2), "=r"(r3) : "r"(a));
}
__device__ __forceinline__ void ldsm_x4_t(uint32_t& r0, uint32_t& r1, uint32_t& r2, uint32_t& r3,
                                          uint32_t a) {
    asm volatile("ldmatrix.sync.aligned.m8n8.x4.trans.shared.b16 {%0,%1,%2,%3}, [%4];"
                 : "=r"(r0), "=r"(r1), "=r"(r2), "=r"(r3) : "r"(a));
}
__device__ __forceinline__ void mma_f16(float& d0, float& d1, float& d2, float& d3,
                                        uint32_t a0, uint32_t a1, uint32_t a2, uint32_t a3,
                                        uint32_t b0, uint32_t b1) {
    asm volatile(
        "mma.sync.aligned.m16n8k16.row.col.f32.f16.f16.f32 "
        "{%0,%1,%2,%3}, {%4,%5,%6,%7}, {%8,%9}, {%0,%1,%2,%3};"
        : "+f"(d0), "+f"(d1), "+f"(d2), "+f"(d3)
        : "r"(a0), "r"(a1), "r"(a2), "r"(a3), "r"(b0), "r"(b1));
}
__device__ __forceinline__ float decay_log(float gamma, int dt) {
    float gd = gamma * fabsf((float)dt) * (1.0f / 511.0f);
    return (gd < 11.0f) ? -gd : logf(expf(-gd) + 1e-8f);
}

// ---------------- f32 -> f16 pre-pass ----------------
__global__ __launch_bounds__(256)
void to_half(const float* __restrict__ src, __half* __restrict__ dst, size_t n4)
{
    size_t i = (size_t)blockIdx.x * blockDim.x + threadIdx.x;
    size_t stride = (size_t)gridDim.x * blockDim.x;
    for (; i < n4; i += stride) {
        float4 v = ((const float4*)src)[i];
        __half2 h0 = __floats2half2_rn(v.x, v.y);
        __half2 h1 = __floats2half2_rn(v.z, v.w);
        uint2 u = { *(uint32_t*)&h0, *(uint32_t*)&h1 };
        ((uint2*)dst)[i] = u;
    }
}

// ---------------- Projection GEMM (fp16 mma, head-major store) ----------------
// Grid (n-tiles=4, m-tiles=1024): adjacent bids share the A tile via L2.
// 3-stage cp.async ring, one __syncthreads per stage.
__global__ __launch_bounds__(256, 2)
void proj_gemm(const __half* __restrict__ Ag, const __half* __restrict__ Bg,
               const float* __restrict__ bias, int which)
{
    extern __shared__ __half sm[];   // 3 bufs x (A 16KB | B 16KB) = 96KB
    const uint32_t smbase = smem_u32(sm);

    const int tid = threadIdx.x;
    const int wid = tid >> 5, lane = tid & 31;
    const int wm = wid >> 2, wn = wid & 3;
    const int m0 = blockIdx.y * 128;
    const int n0 = blockIdx.x * 128;

    const __half* A = Ag + (size_t)m0 * 512;
    const __half* B = Bg + (size_t)n0 * 512;

    const int srow = tid >> 1;
    const int cb0  = (tid & 1) * 4;
    const __half* agp = A + (size_t)srow * 512 + cb0 * 8;
    const __half* bgp = B + (size_t)srow * 512 + cb0 * 8;
    uint32_t swoff[4];
#pragma unroll
    for (int i = 0; i < 4; i++)
        swoff[i] = (uint32_t)srow * 128 + (uint32_t)(((cb0 + i) ^ (srow & 7)) << 4);

    auto issue = [&](int s) {
        uint32_t ab = smbase + (uint32_t)(s % 3) * 32768;
        uint32_t bb = ab + 16384;
        const __half* ag = agp + s * 64;
        const __half* bg = bgp + s * 64;
#pragma unroll
        for (int i = 0; i < 4; i++) {
            cp_async16(ab + swoff[i], ag + i * 8);
            cp_async16(bb + swoff[i], bg + i * 8);
        }
        cp_commit();
    };

    const int mfrag = wm * 64, nfrag = wn * 32;
    const int aChunkLo = lane >> 4;
    const int bChunkLo = (lane >> 3) & 1;
    uint32_t aRowOff[4]; int aSw[4];
#pragma unroll
    for (int mt = 0; mt < 4; mt++) {
        int row = mfrag + mt * 16 + (lane & 15);
        aRowOff[mt] = (uint32_t)row * 128; aSw[mt] = row & 7;
    }
    uint32_t bRowOff[2]; int bSw[2];
#pragma unroll
    for (int ntp = 0; ntp < 2; ntp++) {
        int row = nfrag + ntp * 16 + (lane & 7) + ((lane >> 4) << 3);
        bRowOff[ntp] = (uint32_t)row * 128; bSw[ntp] = row & 7;
    }

    float acc[4][4][4];
#pragma unroll
    for (int mt = 0; mt < 4; mt++)
#pragma unroll
        for (int nt = 0; nt < 4; nt++)
#pragma unroll
            for (int e = 0; e < 4; e++) acc[mt][nt][e] = 0.f;

    issue(0); issue(1);
#pragma unroll 1
    for (int s = 0; s < 8; s++) {
        if (s < 7) cp_wait<1>(); else cp_wait<0>();
        __syncthreads();
        uint32_t ab = smbase + (uint32_t)(s % 3) * 32768;
        uint32_t bb = ab + 16384;
#pragma unroll
        for (int ks = 0; ks < 4; ks++) {
            uint32_t afr[4][4], bfr[4][2];
#pragma unroll
            for (int mt = 0; mt < 4; mt++)
                ldsm_x4(afr[mt][0], afr[mt][1], afr[mt][2], afr[mt][3],
                        ab + aRowOff[mt] + (uint32_t)(((ks * 2 + aChunkLo) ^ aSw[mt]) << 4));
#pragma unroll
            for (int ntp = 0; ntp < 2; ntp++) {
                uint32_t r0, r1, r2, r3;
                ldsm_x4(r0, r1, r2, r3,
                        bb + bRowOff[ntp] + (uint32_t)(((ks * 2 + bChunkLo) ^ bSw[ntp]) << 4));
                bfr[2 * ntp][0] = r0; bfr[2 * ntp][1] = r1;
                bfr[2 * ntp + 1][0] = r2; bfr[2 * ntp + 1][1] = r3;
            }
#pragma unroll
            for (int mt = 0; mt < 4; mt++)
#pragma unroll
                for (int nt = 0; nt < 4; nt++)
                    mma_f16(acc[mt][nt][0], acc[mt][nt][1], acc[mt][nt][2], acc[mt][nt][3],
                            afr[mt][0], afr[mt][1], afr[mt][2], afr[mt][3],
                            bfr[nt][0], bfr[nt][1]);
        }
        if (s + 2 < 8) issue(s + 2);
    }

    // epilogue: head-major store  m=((b*512+t)*64+n) -> dst ((b*64+n)*512+t)*512+c
    const int rq = lane >> 2, kq = lane & 3;
    __half* outp = (which == 0) ? g_Q : (which == 1) ? g_K : g_V;
#pragma unroll
    for (int mt = 0; mt < 4; mt++) {
        const int m = m0 + mfrag + mt * 16 + rq;
        const int b = m >> 15, t = (m >> 6) & 511, n = m & 63;
        __half* dst0 = outp + ((size_t)((b * NHc + n) * Tt + t)) * 512;
#pragma unroll
        for (int nt = 0; nt < 4; nt++) {
            const int c = n0 + nfrag + nt * 8 + kq * 2;
            float2 bv = *(const float2*)(bias + c);
            *(__half2*)(dst0 + c) =
                __floats2half2_rn(acc[mt][nt][0] + bv.x, acc[mt][nt][1] + bv.y);
        }
        const int m8 = m + 8;
        const int b8 = m8 >> 15, t8 = (m8 >> 6) & 511, n8 = m8 & 63;
        __half* dst8 = outp + ((size_t)((b8 * NHc + n8) * Tt + t8)) * 512;
#pragma unroll
        for (int nt = 0; nt < 4; nt++) {
            const int c = n0 + nfrag + nt * 8 + kq * 2;
            float2 bv = *(const float2*)(bias + c);
            *(__half2*)(dst8 + c) =
                __floats2half2_rn(acc[mt][nt][2] + bv.x, acc[mt][nt][3] + bv.y);
        }
    }
}

// ---------------- Fused attention ----------------
// Grid (4 Ti-tiles, 256 heads), 512 threads = 16 warps as 4(m)x4(n).
// smem: P fp16 [128][512] swizzled (128KB) | 3 stage bufs (32KB each)
//       | rsum f32 [4][128] | invl f32 [128]
// Phase 1: flat 32-stage ring (A=Q, B=K via non-trans ldmatrix).
// Phase 2: flat 32-stage ring; V staged NATURALLY [s64][d128] (256B rows) and
//          read with ldmatrix.trans — no separate V-transpose kernel needed.
__global__ __launch_bounds__(512, 1)
void attn_fused(float* __restrict__ Outg,
                const float* __restrict__ lg, const float* __restrict__ lt)
{
    extern __shared__ __half sm[];
    float* rsum = (float*)(sm + 114688);  // after P(128KB)+stages(96KB)
    float* invl = rsum + 512;
    const uint32_t smbase  = smem_u32(sm);
    const uint32_t pbase   = smbase;           // P: [0, 131072)
    const uint32_t stgbase = smbase + 131072;  // 3 x 32KB

    const int tid = threadIdx.x;
    const int wid = tid >> 5, lane = tid & 31;
    const int wm = wid >> 2, wn = wid & 3;
    const int mfrag = wm * 32, nfrag = wn * 32;
    const int rq = lane >> 2, kq = lane & 3;
    const int m0 = blockIdx.x * 128;
    const int h  = blockIdx.y;
    const int b  = h >> 6, n = h & 63;

    const __half* Qh = g_Q + (size_t)h * (Tt * Dd) + (size_t)m0 * 512;
    const __half* Kh = g_K + (size_t)h * (Tt * Dd);
    const __half* Vh = g_V + (size_t)h * (Tt * Dd);

    const float gamma = fmaxf(__expf(*lg), 0.01f);
    const float tau   = fmaxf(__expf(*lt), 0.01f);
    const float scale = 1.0f / (22.62741699796952f * tau);

    // Phase-1 staging: thread -> row tid>>2 (0..127), chunks (tid&3)*2, +1 (128B rows)
    const int srow = tid >> 2;
    const int ch0  = (tid & 3) * 2;
    uint32_t sw[2];
#pragma unroll
    for (int i = 0; i < 2; i++)
        sw[i] = (uint32_t)srow * 128 + (uint32_t)(((ch0 + i) ^ (srow & 7)) << 4);

    // Phase-2 V staging: 64 rows x 256B; thread -> row tid>>3, chunks tid&7, +8
    const int vrow = tid >> 3;
    const int vc0  = tid & 7;
    const uint32_t vswA = (uint32_t)vrow * 256 + (uint32_t)((vc0 ^ (vrow & 7)) << 4);
    const uint32_t vswB = vswA + 128;   // chunk+8: bit3 untouched by ^(row&7)

    const int aChunkLo = lane >> 4;
    const int bChunkLo = (lane >> 3) & 1;
    uint32_t aRowOff[2]; int aSw[2];
#pragma unroll
    for (int mt = 0; mt < 2; mt++) {
        int row = mfrag + mt * 16 + (lane & 15);
        aRowOff[mt] = (uint32_t)row * 128; aSw[mt] = row & 7;
    }
    uint32_t bRowOff[2]; int bSw[2];
#pragma unroll
    for (int ntp = 0; ntp < 2; ntp++) {
        int row = nfrag + ntp * 16 + (lane & 7) + ((lane >> 4) << 3);
        bRowOff[ntp] = (uint32_t)row * 128; bSw[ntp] = row & 7;
    }
    uint32_t pRowOff[2]; int pSw[2];
#pragma unroll
    for (int mt = 0; mt < 2; mt++) {
        int row = mfrag + mt * 16 + (lane & 15);
        pRowOff[mt] = (uint32_t)row * 1024; pSw[mt] = row & 7;
    }

    float rs[4] = {0.f, 0.f, 0.f, 0.f};
    const __half* Arow = Qh + (size_t)srow * 512 + ch0 * 8;

    // =============== Phase 1: flat 32 stages (4 jt x 8 k-stages) ===============
    auto issue1 = [&](int s) {
        const int jt = s >> 3, sk = s & 7;
        uint32_t ab = stgbase + (uint32_t)(s % 3) * 32768;
        uint32_t bb = ab + 16384;
        const __half* ag = Arow + sk * 64;
        const __half* bg = Kh + (size_t)(jt * 128 + srow) * 512 + ch0 * 8 + sk * 64;
#pragma unroll
        for (int i = 0; i < 2; i++) {
            cp_async16(ab + sw[i], ag + i * 8);
            cp_async16(bb + sw[i], bg + i * 8);
        }
        cp_commit();
    };

    float acc[2][4][4];
#pragma unroll
    for (int mt = 0; mt < 2; mt++)
#pragma unroll
        for (int nt = 0; nt < 4; nt++)
#pragma unroll
            for (int e = 0; e < 4; e++) acc[mt][nt][e] = 0.f;

    issue1(0); issue1(1);
#pragma unroll 1
    for (int s = 0; s < 32; s++) {
        if (s < 31) cp_wait<1>(); else cp_wait<0>();
        __syncthreads();
        uint32_t ab = stgbase + (uint32_t)(s % 3) * 32768;
        uint32_t bb = ab + 16384;
#pragma unroll
        for (int ks = 0; ks < 4; ks++) {
            uint32_t afr[2][4], bfr[4][2];
#pragma unroll
            for (int mt = 0; mt < 2; mt++)
                ldsm_x4(afr[mt][0], afr[mt][1], afr[mt][2], afr[mt][3],
                        ab + aRowOff[mt] + (uint32_t)(((ks * 2 + aChunkLo) ^ aSw[mt]) << 4));
#pragma unroll
            for (int ntp = 0; ntp < 2; ntp++) {
                uint32_t r0, r1, r2, r3;
                ldsm_x4(r0, r1, r2, r3,
                        bb + bRowOff[ntp] + (uint32_t)(((ks * 2 + bChunkLo) ^ bSw[ntp]) << 4));
                bfr[2 * ntp][0] = r0; bfr[2 * ntp][1] = r1;
                bfr[2 * ntp + 1][0] = r2; bfr[2 * ntp + 1][1] = r3;
            }
#pragma unroll
            for (int mt = 0; mt < 2; mt++)
#pragma unroll
                for (int nt = 0; nt < 4; nt++)
                    mma_f16(acc[mt][nt][0], acc[mt][nt][1], acc[mt][nt][2], acc[mt][nt][3],
                            afr[mt][0], afr[mt][1], afr[mt][2], afr[mt][3],
                            bfr[nt][0], bfr[nt][1]);
        }
        if (s + 2 < 32) issue1(s + 2);

        if ((s & 7) == 7) {
            // jt tile complete: bias + exp + store P + rowsum, reset acc
            const int jt = s >> 3;
#pragma unroll
            for (int mt = 0; mt < 2; mt++) {
                const int r  = mfrag + mt * 16 + rq;
                const int t0 = m0 + r, t1 = t0 + 8;
#pragma unroll
                for (int nt = 0; nt < 4; nt++) {
                    const int c  = nfrag + nt * 8 + kq * 2;
                    const int sg = jt * 128 + c;
                    float e00 = __expf(fmaf(acc[mt][nt][0], scale, decay_log(gamma, t0 - sg)));
                    float e01 = __expf(fmaf(acc[mt][nt][1], scale, decay_log(gamma, t0 - sg - 1)));
                    float e10 = __expf(fmaf(acc[mt][nt][2], scale, decay_log(gamma, t1 - sg)));
                    float e11 = __expf(fmaf(acc[mt][nt][3], scale, decay_log(gamma, t1 - sg - 1)));
                    uint32_t hoff0 = (uint32_t)r * 512 + (uint32_t)((((sg >> 3) ^ (r & 7)) << 3) + (sg & 7));
                    uint32_t hoff1 = (uint32_t)(r + 8) * 512 + (uint32_t)((((sg >> 3) ^ ((r + 8) & 7)) << 3) + (sg & 7));
                    *(__half2*)(sm + hoff0) = __floats2half2_rn(e00, e01);
                    *(__half2*)(sm + hoff1) = __floats2half2_rn(e10, e11);
                    rs[mt * 2 + 0] += e00 + e01;
                    rs[mt * 2 + 1] += e10 + e11;
                    acc[mt][nt][0] = 0.f; acc[mt][nt][1] = 0.f;
                    acc[mt][nt][2] = 0.f; acc[mt][nt][3] = 0.f;
                }
            }
        }
    }

    // rowsum reduce
#pragma unroll
    for (int i = 0; i < 4; i++) {
        rs[i] += __shfl_xor_sync(0xffffffffu, rs[i], 1);
        rs[i] += __shfl_xor_sync(0xffffffffu, rs[i], 2);
    }
    if (kq == 0) {
#pragma unroll
        for (int mt = 0; mt < 2; mt++) {
            const int r = mfrag + mt * 16 + rq;
            rsum[wn * 128 + r]     = rs[mt * 2 + 0];
            rsum[wn * 128 + r + 8] = rs[mt * 2 + 1];
        }
    }
    __syncthreads();
    if (tid < 128)
        invl[tid] = 1.0f / (rsum[tid] + rsum[128 + tid] + rsum[256 + tid] + rsum[384 + tid]);
    __syncthreads();

    // =============== Phase 2: flat 32 stages (4 dc x 8 sk-stages) ===============
    // V staged naturally: stage = [s-rows 64][d 128] fp16 (256B rows), trans ldmatrix.
    auto issue2 = [&](int s) {
        const int dc = s >> 3, sk = s & 7;
        uint32_t bb = stgbase + (uint32_t)(s % 3) * 32768 + 16384;
        const __half* bg = Vh + (size_t)(sk * 64 + vrow) * 512 + dc * 128;
        cp_async16(bb + vswA, bg + vc0 * 8);
        cp_async16(bb + vswB, bg + (vc0 + 8) * 8);
        cp_commit();
    };

    issue2(0); issue2(1);
#pragma unroll 1
    for (int s = 0; s < 32; s++) {
        if (s < 31) cp_wait<1>(); else cp_wait<0>();
        __syncthreads();
        const int sk = s & 7;
        uint32_t bb = stgbase + (uint32_t)(s % 3) * 32768 + 16384;
#pragma unroll
        for (int ks = 0; ks < 4; ks++) {
            uint32_t afr[2][4], bfr[4][2];
#pragma unroll
            for (int mt = 0; mt < 2; mt++) {
                uint32_t achunk = (uint32_t)(sk * 8 + ks * 2 + aChunkLo);
                ldsm_x4(afr[mt][0], afr[mt][1], afr[mt][2], afr[mt][3],
                        pbase + pRowOff[mt] + ((achunk ^ (uint32_t)pSw[mt]) << 4));
            }
            const int rowk = ks * 16 + (lane & 15);
#pragma unroll
            for (int ntp = 0; ntp < 2; ntp++) {
                uint32_t chunk = (uint32_t)((nfrag >> 3) + ntp * 2 + (lane >> 4));
                uint32_t addr = bb + (uint32_t)rowk * 256
                              + ((chunk ^ (uint32_t)(rowk & 7)) << 4);
                uint32_t r0, r1, r2, r3;
                ldsm_x4_t(r0, r1, r2, r3, addr);
                bfr[2 * ntp][0] = r0; bfr[2 * ntp][1] = r1;
                bfr[2 * ntp + 1][0] = r2; bfr[2 * ntp + 1][1] = r3;
            }
#pragma unroll
            for (int mt = 0; mt < 2; mt++)
#pragma unroll
                for (int nt = 0; nt < 4; nt++)
                    mma_f16(acc[mt][nt][0], acc[mt][nt][1], acc[mt][nt][2], acc[mt][nt][3],
                            afr[mt][0], afr[mt][1], afr[mt][2], afr[mt][3],
                            bfr[nt][0], bfr[nt][1]);
        }
        if (s + 2 < 32) issue2(s + 2);

        if ((s & 7) == 7) {
            const int dc = s >> 3;
#pragma unroll
            for (int mt = 0; mt < 2; mt++) {
                const int r = mfrag + mt * 16 + rq;
                const float il0 = invl[r], il1 = invl[r + 8];
                const int t0 = m0 + r;
                float* dst0 = Outg + (((size_t)(b * Tt + t0) * NHc + n) << 9);
                float* dst1 = Outg + (((size_t)(b * Tt + t0 + 8) * NHc + n) << 9);
#pragma unroll
                for (int nt = 0; nt < 4; nt++) {
                    const int c = dc * 128 + nfrag + nt * 8 + kq * 2;
                    float2 v0 = { acc[mt][nt][0] * il0, acc[mt][nt][1] * il0 };
                    float2 v1 = { acc[mt][nt][2] * il1, acc[mt][nt][3] * il1 };
                    *(float2*)(dst0 + c) = v0;
                    *(float2*)(dst1 + c) = v1;
                    acc[mt][nt][0] = 0.f; acc[mt][nt][1] = 0.f;
                    acc[mt][nt][2] = 0.f; acc[mt][nt][3] = 0.f;
                }
            }
        }
    }
}

extern "C" void kernel_launch(void* const* d_in, const int* in_sizes, int n_in,
                              void* d_out, int out_size)
{
    const float* H_i = (const float*)d_in[0];
    const float* H_j = (const float*)d_in[1];
    const float* Wq  = (const float*)d_in[2];
    const float* bq  = (const float*)d_in[3];
    const float* Wk  = (const float*)d_in[4];
    const float* bk  = (const float*)d_in[5];
    const float* Wv  = (const float*)d_in[6];
    const float* bv  = (const float*)d_in[7];
    const float* lg  = (const float*)d_in[8];
    const float* lt  = (const float*)d_in[9];
    float* out = (float*)d_out;

    __half *p_Hi, *p_Hj, *p_Wq, *p_Wk, *p_Wv;
    cudaGetSymbolAddress((void**)&p_Hi, g_Hi);
    cudaGetSymbolAddress((void**)&p_Hj, g_Hj);
    cudaGetSymbolAddress((void**)&p_Wq, g_Wq);
    cudaGetSymbolAddress((void**)&p_Wk, g_Wk);
    cudaGetSymbolAddress((void**)&p_Wv, g_Wv);

    to_half<<<8192, 256>>>(H_i, p_Hi, (size_t)MPROJ * Dd / 4);
    to_half<<<8192, 256>>>(H_j, p_Hj, (size_t)MPROJ * Dd / 4);
    to_half<<<256, 256>>>(Wq, p_Wq, (size_t)Dd * Dd / 4);
    to_half<<<256, 256>>>(Wk, p_Wk, (size_t)Dd * Dd / 4);
    to_half<<<256, 256>>>(Wv, p_Wv, (size_t)Dd * Dd / 4);

    const int proj_shmem = 3 * 32768;  // 96KB
    cudaFuncSetAttribute(proj_gemm, cudaFuncAttributeMaxDynamicSharedMemorySize, proj_shmem);

    dim3 blk(256);
    dim3 gproj(4, MPROJ / 128, 1);     // x = n-tile (L2-shared A), y = m-tile
    proj_gemm<<<gproj, blk, proj_shmem>>>(p_Hi, p_Wq, bq, 0);
    proj_gemm<<<gproj, blk, proj_shmem>>>(p_Hj, p_Wk, bk, 1);
    proj_gemm<<<gproj, blk, proj_shmem>>>(p_Hj, p_Wv, bv, 2);

    // P 128KB + 3x32KB stages + rsum(2KB) + invl(512B) = 231936 B
    const int attn_shmem = 131072 + 98304 + 2048 + 512;
    cudaFuncSetAttribute(attn_fused, cudaFuncAttributeMaxDynamicSharedMemorySize, attn_shmem);
    attn_fused<<<dim3(4, NHEADS), 512, attn_shmem>>>(out, lg, lt);
}

// round 9
// speedup vs baseline: 6.0349x; 1.0074x over previous
#include <cuda_runtime.h>
#include <cuda_fp16.h>
#include <cstdint>
#include <math.h>

constexpr int Tt = 512, NHc = 64, Dd = 512, Bb = 4;
constexpr int NHEADS = Bb * NHc;        // 256
constexpr int MPROJ  = Bb * Tt * NHc;   // 131072

// Scratch (device globals; no cudaMalloc allowed)
__device__ __half g_Hi[(size_t)MPROJ * Dd];
__device__ __half g_Hj[(size_t)MPROJ * Dd];
__device__ __half g_Wq[(size_t)Dd * Dd];
__device__ __half g_Wk[(size_t)Dd * Dd];
__device__ __half g_Wv[(size_t)Dd * Dd];
__device__ __half g_Q [(size_t)MPROJ * Dd];        // [B,N,T,D] head-major
__device__ __half g_K [(size_t)MPROJ * Dd];        // [B,N,S,D] head-major
__device__ __half g_V [(size_t)MPROJ * Dd];        // [B,N,S,D] head-major

__device__ __forceinline__ uint32_t smem_u32(const void* p) {
    uint32_t a;
    asm("{ .reg .u64 t; cvta.to.shared.u64 t, %1; cvt.u32.u64 %0, t; }" : "=r"(a) : "l"(p));
    return a;
}
__device__ __forceinline__ void cp_async16(uint32_t saddr, const void* gptr) {
    asm volatile("cp.async.cg.shared.global [%0], [%1], 16;" :: "r"(saddr), "l"(gptr));
}
__device__ __forceinline__ void cp_commit() {
    asm volatile("cp.async.commit_group;" ::: "memory");
}
template<int N> __device__ __forceinline__ void cp_wait() {
    asm volatile("cp.async.wait_group %0;" :: "n"(N) : "memory");
}
__device__ __forceinline__ void ldsm_x4(uint32_t& r0, uint32_t& r1, uint32_t& r2, uint32_t& r3,
                                        uint32_t a) {
    asm volatile("ldmatrix.sync.aligned.m8n8.x4.shared.b16 {%0,%1,%2,%3}, [%4];"
                 : "=r"(r0), "=r"(r1), "=r"(r2), "=r"(r3) : "r"(a));
}
__device__ __forceinline__ void ldsm_x4_t(uint32_t& r0, uint32_t& r1, uint32_t& r2, uint32_t& r3,
                                          uint32_t a) {
    asm volatile("ldmatrix.sync.aligned.m8n8.x4.trans.shared.b16 {%0,%1,%2,%3}, [%4];"
                 : "=r"(r0), "=r"(r1), "=r"(r2), "=r"(r3) : "r"(a));
}
__device__ __forceinline__ void mma_f16(float& d0, float& d1, float& d2, float& d3,
                                        uint32_t a0, uint32_t a1, uint32_t a2, uint32_t a3,
                                        uint32_t b0, uint32_t b1) {
    asm volatile(
        "mma.sync.aligned.m16n8k16.row.col.f32.f16.f16.f32 "
        "{%0,%1,%2,%3}, {%4,%5,%6,%7}, {%8,%9}, {%0,%1,%2,%3};"
        : "+f"(d0), "+f"(d1), "+f"(d2), "+f"(d3)
        : "r"(a0), "r"(a1), "r"(a2), "r"(a3), "r"(b0), "r"(b1));
}
__device__ __forceinline__ float decay_log(float gamma, int dt) {
    float gd = gamma * fabsf((float)dt) * (1.0f / 511.0f);
    return (gd < 11.0f) ? -gd : logf(expf(-gd) + 1e-8f);
}

// ---------------- f32 -> f16 pre-pass ----------------
__global__ __launch_bounds__(256)
void to_half(const float* __restrict__ src, __half* __restrict__ dst, size_t n4)
{
    size_t i = (size_t)blockIdx.x * blockDim.x + threadIdx.x;
    size_t stride = (size_t)gridDim.x * blockDim.x;
    for (; i < n4; i += stride) {
        float4 v = ((const float4*)src)[i];
        __half2 h0 = __floats2half2_rn(v.x, v.y);
        __half2 h1 = __floats2half2_rn(v.z, v.w);
        uint2 u = { *(uint32_t*)&h0, *(uint32_t*)&h1 };
        ((uint2*)dst)[i] = u;
    }
}

// ---------------- Projection GEMM (fp16 mma, head-major store) ----------------
__global__ __launch_bounds__(256, 2)
void proj_gemm(const __half* __restrict__ Ag, const __half* __restrict__ Bg,
               const float* __restrict__ bias, int which)
{
    extern __shared__ __half sm[];   // 3 bufs x (A 16KB | B 16KB) = 96KB
    const uint32_t smbase = smem_u32(sm);

    const int tid = threadIdx.x;
    const int wid = tid >> 5, lane = tid & 31;
    const int wm = wid >> 2, wn = wid & 3;
    const int m0 = blockIdx.y * 128;
    const int n0 = blockIdx.x * 128;

    const __half* A = Ag + (size_t)m0 * 512;
    const __half* B = Bg + (size_t)n0 * 512;

    const int srow = tid >> 1;
    const int cb0  = (tid & 1) * 4;
    const __half* agp = A + (size_t)srow * 512 + cb0 * 8;
    const __half* bgp = B + (size_t)srow * 512 + cb0 * 8;
    uint32_t swoff[4];
#pragma unroll
    for (int i = 0; i < 4; i++)
        swoff[i] = (uint32_t)srow * 128 + (uint32_t)(((cb0 + i) ^ (srow & 7)) << 4);

    auto issue = [&](int s) {
        uint32_t ab = smbase + (uint32_t)(s % 3) * 32768;
        uint32_t bb = ab + 16384;
        const __half* ag = agp + s * 64;
        const __half* bg = bgp + s * 64;
#pragma unroll
        for (int i = 0; i < 4; i++) {
            cp_async16(ab + swoff[i], ag + i * 8);
            cp_async16(bb + swoff[i], bg + i * 8);
        }
        cp_commit();
    };

    const int mfrag = wm * 64, nfrag = wn * 32;
    const int aChunkLo = lane >> 4;
    const int bChunkLo = (lane >> 3) & 1;
    uint32_t aRowOff[4]; int aSw[4];
#pragma unroll
    for (int mt = 0; mt < 4; mt++) {
        int row = mfrag + mt * 16 + (lane & 15);
        aRowOff[mt] = (uint32_t)row * 128; aSw[mt] = row & 7;
    }
    uint32_t bRowOff[2]; int bSw[2];
#pragma unroll
    for (int ntp = 0; ntp < 2; ntp++) {
        int row = nfrag + ntp * 16 + (lane & 7) + ((lane >> 4) << 3);
        bRowOff[ntp] = (uint32_t)row * 128; bSw[ntp] = row & 7;
    }

    float acc[4][4][4];
#pragma unroll
    for (int mt = 0; mt < 4; mt++)
#pragma unroll
        for (int nt = 0; nt < 4; nt++)
#pragma unroll
            for (int e = 0; e < 4; e++) acc[mt][nt][e] = 0.f;

    issue(0); issue(1);
#pragma unroll 1
    for (int s = 0; s < 8; s++) {
        if (s < 7) cp_wait<1>(); else cp_wait<0>();
        __syncthreads();
        uint32_t ab = smbase + (uint32_t)(s % 3) * 32768;
        uint32_t bb = ab + 16384;
#pragma unroll
        for (int ks = 0; ks < 4; ks++) {
            uint32_t afr[4][4], bfr[4][2];
#pragma unroll
            for (int mt = 0; mt < 4; mt++)
                ldsm_x4(afr[mt][0], afr[mt][1], afr[mt][2], afr[mt][3],
                        ab + aRowOff[mt] + (uint32_t)(((ks * 2 + aChunkLo) ^ aSw[mt]) << 4));
#pragma unroll
            for (int ntp = 0; ntp < 2; ntp++) {
                uint32_t r0, r1, r2, r3;
                ldsm_x4(r0, r1, r2, r3,
                        bb + bRowOff[ntp] + (uint32_t)(((ks * 2 + bChunkLo) ^ bSw[ntp]) << 4));
                bfr[2 * ntp][0] = r0; bfr[2 * ntp][1] = r1;
                bfr[2 * ntp + 1][0] = r2; bfr[2 * ntp + 1][1] = r3;
            }
#pragma unroll
            for (int mt = 0; mt < 4; mt++)
#pragma unroll
                for (int nt = 0; nt < 4; nt++)
                    mma_f16(acc[mt][nt][0], acc[mt][nt][1], acc[mt][nt][2], acc[mt][nt][3],
                            afr[mt][0], afr[mt][1], afr[mt][2], afr[mt][3],
                            bfr[nt][0], bfr[nt][1]);
        }
        if (s + 2 < 8) issue(s + 2);
    }

    const int rq = lane >> 2, kq = lane & 3;
    __half* outp = (which == 0) ? g_Q : (which == 1) ? g_K : g_V;
#pragma unroll
    for (int mt = 0; mt < 4; mt++) {
        const int m = m0 + mfrag + mt * 16 + rq;
        const int b = m >> 15, t = (m >> 6) & 511, n = m & 63;
        __half* dst0 = outp + ((size_t)((b * NHc + n) * Tt + t)) * 512;
#pragma unroll
        for (int nt = 0; nt < 4; nt++) {
            const int c = n0 + nfrag + nt * 8 + kq * 2;
            float2 bv = *(const float2*)(bias + c);
            *(__half2*)(dst0 + c) =
                __floats2half2_rn(acc[mt][nt][0] + bv.x, acc[mt][nt][1] + bv.y);
        }
        const int m8 = m + 8;
        const int b8 = m8 >> 15, t8 = (m8 >> 6) & 511, n8 = m8 & 63;
        __half* dst8 = outp + ((size_t)((b8 * NHc + n8) * Tt + t8)) * 512;
#pragma unroll
        for (int nt = 0; nt < 4; nt++) {
            const int c = n0 + nfrag + nt * 8 + kq * 2;
            float2 bv = *(const float2*)(bias + c);
            *(__half2*)(dst8 + c) =
                __floats2half2_rn(acc[mt][nt][2] + bv.x, acc[mt][nt][3] + bv.y);
        }
    }
}

// ---------------- Fused attention ----------------
// Grid (4 Ti-tiles, 256 heads), 512 threads = 16 warps.
// Phase 1 (4m x 4n warps, 32x32 tile): S tiles jt=0..3, exp->P smem, rowsums.
//   3-slot ring of 32KB stages (A=Q 16KB, B=K 16KB).
// Phase 2 (4m x 4n warps, 32x64 tile): O = P @ V^T in 2 passes of 256 d-cols.
//   V staged naturally [s32][d256] (512B rows), 6-slot ring of 16KB stages,
//   5-ahead prefetch, trans-ldmatrix B reads. V traffic & P re-reads halved.
__global__ __launch_bounds__(512, 1)
void attn_fused(float* __restrict__ Outg,
                const float* __restrict__ lg, const float* __restrict__ lt)
{
    extern __shared__ __half sm[];
    float* rsum = (float*)(sm + 114688);  // after P(128KB)+stages(96KB)
    float* invl = rsum + 512;
    const uint32_t smbase  = smem_u32(sm);
    const uint32_t pbase   = smbase;           // P: [0, 131072)
    const uint32_t stgbase = smbase + 131072;  // 96KB stage region

    const int tid = threadIdx.x;
    const int wid = tid >> 5, lane = tid & 31;
    const int wm = wid >> 2, wn = wid & 3;
    const int mfrag = wm * 32;
    const int nfrag = wn * 32;      // phase-1 n base (32-wide)
    const int nfrag2 = wn * 64;     // phase-2 n base (64-wide)
    const int rq = lane >> 2, kq = lane & 3;
    const int m0 = blockIdx.x * 128;
    const int h  = blockIdx.y;
    const int b  = h >> 6, n = h & 63;

    const __half* Qh = g_Q + (size_t)h * (Tt * Dd) + (size_t)m0 * 512;
    const __half* Kh = g_K + (size_t)h * (Tt * Dd);
    const __half* Vh = g_V + (size_t)h * (Tt * Dd);

    const float gamma = fmaxf(__expf(*lg), 0.01f);
    const float tau   = fmaxf(__expf(*lt), 0.01f);
    const float scale = 1.0f / (22.62741699796952f * tau);

    // Phase-1 staging (128B rows): thread -> row tid>>2, chunks (tid&3)*2, +1
    const int srow = tid >> 2;
    const int ch0  = (tid & 3) * 2;
    uint32_t sw[2];
#pragma unroll
    for (int i = 0; i < 2; i++)
        sw[i] = (uint32_t)srow * 128 + (uint32_t)(((ch0 + i) ^ (srow & 7)) << 4);

    // Phase-2 V staging (512B rows, 32 rows/stage): row tid>>4, chunks tid&15, +16
    const int vrow = tid >> 4;
    const int vc0  = tid & 15;
    const uint32_t vswA = (uint32_t)vrow * 512 + (uint32_t)((vc0 ^ (vrow & 7)) << 4);
    const uint32_t vswB = vswA + 256;   // chunk+16: bit4 untouched by ^(row&7)

    const int aChunkLo = lane >> 4;
    const int bChunkLo = (lane >> 3) & 1;
    uint32_t aRowOff[2]; int aSw[2];
#pragma unroll
    for (int mt = 0; mt < 2; mt++) {
        int row = mfrag + mt * 16 + (lane & 15);
        aRowOff[mt] = (uint32_t)row * 128; aSw[mt] = row & 7;
    }
    uint32_t bRowOff[2]; int bSw[2];
#pragma unroll
    for (int ntp = 0; ntp < 2; ntp++) {
        int row = nfrag + ntp * 16 + (lane & 7) + ((lane >> 4) << 3);
        bRowOff[ntp] = (uint32_t)row * 128; bSw[ntp] = row & 7;
    }
    uint32_t pRowOff[2]; int pSw[2];
#pragma unroll
    for (int mt = 0; mt < 2; mt++) {
        int row = mfrag + mt * 16 + (lane & 15);
        pRowOff[mt] = (uint32_t)row * 1024; pSw[mt] = row & 7;
    }

    float rs[4] = {0.f, 0.f, 0.f, 0.f};
    const __half* Arow = Qh + (size_t)srow * 512 + ch0 * 8;

    // =============== Phase 1: flat 32 stages (4 jt x 8 k-stages) ===============
    auto issue1 = [&](int s) {
        const int jt = s >> 3, sk = s & 7;
        uint32_t ab = stgbase + (uint32_t)(s % 3) * 32768;
        uint32_t bb = ab + 16384;
        const __half* ag = Arow + sk * 64;
        const __half* bg = Kh + (size_t)(jt * 128 + srow) * 512 + ch0 * 8 + sk * 64;
#pragma unroll
        for (int i = 0; i < 2; i++) {
            cp_async16(ab + sw[i], ag + i * 8);
            cp_async16(bb + sw[i], bg + i * 8);
        }
        cp_commit();
    };

    {
        float acc[2][4][4];
#pragma unroll
        for (int mt = 0; mt < 2; mt++)
#pragma unroll
            for (int nt = 0; nt < 4; nt++)
#pragma unroll
                for (int e = 0; e < 4; e++) acc[mt][nt][e] = 0.f;

        issue1(0); issue1(1);
#pragma unroll 1
        for (int s = 0; s < 32; s++) {
            if (s < 31) cp_wait<1>(); else cp_wait<0>();
            __syncthreads();
            uint32_t ab = stgbase + (uint32_t)(s % 3) * 32768;
            uint32_t bb = ab + 16384;
#pragma unroll
            for (int ks = 0; ks < 4; ks++) {
                uint32_t afr[2][4], bfr[4][2];
#pragma unroll
                for (int mt = 0; mt < 2; mt++)
                    ldsm_x4(afr[mt][0], afr[mt][1], afr[mt][2], afr[mt][3],
                            ab + aRowOff[mt] + (uint32_t)(((ks * 2 + aChunkLo) ^ aSw[mt]) << 4));
#pragma unroll
                for (int ntp = 0; ntp < 2; ntp++) {
                    uint32_t r0, r1, r2, r3;
                    ldsm_x4(r0, r1, r2, r3,
                            bb + bRowOff[ntp] + (uint32_t)(((ks * 2 + bChunkLo) ^ bSw[ntp]) << 4));
                    bfr[2 * ntp][0] = r0; bfr[2 * ntp][1] = r1;
                    bfr[2 * ntp + 1][0] = r2; bfr[2 * ntp + 1][1] = r3;
                }
#pragma unroll
                for (int mt = 0; mt < 2; mt++)
#pragma unroll
                    for (int nt = 0; nt < 4; nt++)
                        mma_f16(acc[mt][nt][0], acc[mt][nt][1], acc[mt][nt][2], acc[mt][nt][3],
                                afr[mt][0], afr[mt][1], afr[mt][2], afr[mt][3],
                                bfr[nt][0], bfr[nt][1]);
            }
            if (s + 2 < 32) issue1(s + 2);

            if ((s & 7) == 7) {
                const int jt = s >> 3;
#pragma unroll
                for (int mt = 0; mt < 2; mt++) {
                    const int r  = mfrag + mt * 16 + rq;
                    const int t0 = m0 + r, t1 = t0 + 8;
#pragma unroll
                    for (int nt = 0; nt < 4; nt++) {
                        const int c  = nfrag + nt * 8 + kq * 2;
                        const int sg = jt * 128 + c;
                        float e00 = __expf(fmaf(acc[mt][nt][0], scale, decay_log(gamma, t0 - sg)));
                        float e01 = __expf(fmaf(acc[mt][nt][1], scale, decay_log(gamma, t0 - sg - 1)));
                        float e10 = __expf(fmaf(acc[mt][nt][2], scale, decay_log(gamma, t1 - sg)));
                        float e11 = __expf(fmaf(acc[mt][nt][3], scale, decay_log(gamma, t1 - sg - 1)));
                        uint32_t hoff0 = (uint32_t)r * 512 + (uint32_t)((((sg >> 3) ^ (r & 7)) << 3) + (sg & 7));
                        uint32_t hoff1 = (uint32_t)(r + 8) * 512 + (uint32_t)((((sg >> 3) ^ ((r + 8) & 7)) << 3) + (sg & 7));
                        *(__half2*)(sm + hoff0) = __floats2half2_rn(e00, e01);
                        *(__half2*)(sm + hoff1) = __floats2half2_rn(e10, e11);
                        rs[mt * 2 + 0] += e00 + e01;
                        rs[mt * 2 + 1] += e10 + e11;
                        acc[mt][nt][0] = 0.f; acc[mt][nt][1] = 0.f;
                        acc[mt][nt][2] = 0.f; acc[mt][nt][3] = 0.f;
                    }
                }
            }
        }
    }

    // rowsum reduce
#pragma unroll
    for (int i = 0; i < 4; i++) {
        rs[i] += __shfl_xor_sync(0xffffffffu, rs[i], 1);
        rs[i] += __shfl_xor_sync(0xffffffffu, rs[i], 2);
    }
    if (kq == 0) {
#pragma unroll
        for (int mt = 0; mt < 2; mt++) {
            const int r = mfrag + mt * 16 + rq;
            rsum[wn * 128 + r]     = rs[mt * 2 + 0];
            rsum[wn * 128 + r + 8] = rs[mt * 2 + 1];
        }
    }
    __syncthreads();
    if (tid < 128)
        invl[tid] = 1.0f / (rsum[tid] + rsum[128 + tid] + rsum[256 + tid] + rsum[384 + tid]);
    __syncthreads();

    // =============== Phase 2: 2 dc passes x 16 s-stages, 6-slot ring ===============
    auto issue2 = [&](int s) {
        const int dc = s >> 4, sk = s & 15;
        uint32_t bb = stgbase + (uint32_t)(s % 6) * 16384;
        const __half* bg = Vh + (size_t)(sk * 32 + vrow) * 512 + dc * 256;
        cp_async16(bb + vswA, bg + vc0 * 8);
        cp_async16(bb + vswB, bg + (vc0 + 16) * 8);
        cp_commit();
    };

    {
        float acc[2][8][4];
#pragma unroll
        for (int mt = 0; mt < 2; mt++)
#pragma unroll
            for (int nt = 0; nt < 8; nt++)
#pragma unroll
                for (int e = 0; e < 4; e++) acc[mt][nt][e] = 0.f;

        issue2(0); issue2(1); issue2(2); issue2(3); issue2(4);
#pragma unroll 1
        for (int s = 0; s < 32; s++) {
            if (s <= 27)      cp_wait<4>();
            else if (s == 28) cp_wait<3>();
            else if (s == 29) cp_wait<2>();
            else if (s == 30) cp_wait<1>();
            else              cp_wait<0>();
            __syncthreads();
            const int sk = s & 15;
            uint32_t bb = stgbase + (uint32_t)(s % 6) * 16384;
#pragma unroll
            for (int ks = 0; ks < 2; ks++) {
                uint32_t afr[2][4], bfr[8][2];
                const uint32_t achunk = (uint32_t)((sk * 2 + ks) * 2 + aChunkLo);
#pragma unroll
                for (int mt = 0; mt < 2; mt++)
                    ldsm_x4(afr[mt][0], afr[mt][1], afr[mt][2], afr[mt][3],
                            pbase + pRowOff[mt] + ((achunk ^ (uint32_t)pSw[mt]) << 4));
                const int rowk = ks * 16 + (lane & 15);
#pragma unroll
                for (int ntp = 0; ntp < 4; ntp++) {
                    uint32_t chunk = (uint32_t)((nfrag2 >> 3) + ntp * 2 + (lane >> 4));
                    uint32_t addr = bb + (uint32_t)rowk * 512
                                  + ((chunk ^ (uint32_t)(rowk & 7)) << 4);
                    uint32_t r0, r1, r2, r3;
                    ldsm_x4_t(r0, r1, r2, r3, addr);
                    bfr[2 * ntp][0] = r0; bfr[2 * ntp][1] = r1;
                    bfr[2 * ntp + 1][0] = r2; bfr[2 * ntp + 1][1] = r3;
                }
#pragma unroll
                for (int mt = 0; mt < 2; mt++)
#pragma unroll
                    for (int nt = 0; nt < 8; nt++)
                        mma_f16(acc[mt][nt][0], acc[mt][nt][1], acc[mt][nt][2], acc[mt][nt][3],
                                afr[mt][0], afr[mt][1], afr[mt][2], afr[mt][3],
                                bfr[nt][0], bfr[nt][1]);
            }
            if (s + 5 < 32) issue2(s + 5);

            if ((s & 15) == 15) {
                const int dc = s >> 4;
#pragma unroll
                for (int mt = 0; mt < 2; mt++) {
                    const int r = mfrag + mt * 16 + rq;
                    const float il0 = invl[r], il1 = invl[r + 8];
                    const int t0 = m0 + r;
                    float* dst0 = Outg + (((size_t)(b * Tt + t0) * NHc + n) << 9);
                    float* dst1 = Outg + (((size_t)(b * Tt + t0 + 8) * NHc + n) << 9);
#pragma unroll
                    for (int nt = 0; nt < 8; nt++) {
                        const int c = dc * 256 + nfrag2 + nt * 8 + kq * 2;
                        float2 v0 = { acc[mt][nt][0] * il0, acc[mt][nt][1] * il0 };
                        float2 v1 = { acc[mt][nt][2] * il1, acc[mt][nt][3] * il1 };
                        *(float2*)(dst0 + c) = v0;
                        *(float2*)(dst1 + c) = v1;
                        acc[mt][nt][0] = 0.f; acc[mt][nt][1] = 0.f;
                        acc[mt][nt][2] = 0.f; acc[mt][nt][3] = 0.f;
                    }
                }
            }
        }
    }
}

extern "C" void kernel_launch(void* const* d_in, const int* in_sizes, int n_in,
                              void* d_out, int out_size)
{
    const float* H_i = (const float*)d_in[0];
    const float* H_j = (const float*)d_in[1];
    const float* Wq  = (const float*)d_in[2];
    const float* bq  = (const float*)d_in[3];
    const float* Wk  = (const float*)d_in[4];
    const float* bk  = (const float*)d_in[5];
    const float* Wv  = (const float*)d_in[6];
    const float* bv  = (const float*)d_in[7];
    const float* lg  = (const float*)d_in[8];
    const float* lt  = (const float*)d_in[9];
    float* out = (float*)d_out;

    __half *p_Hi, *p_Hj, *p_Wq, *p_Wk, *p_Wv;
    cudaGetSymbolAddress((void**)&p_Hi, g_Hi);
    cudaGetSymbolAddress((void**)&p_Hj, g_Hj);
    cudaGetSymbolAddress((void**)&p_Wq, g_Wq);
    cudaGetSymbolAddress((void**)&p_Wk, g_Wk);
    cudaGetSymbolAddress((void**)&p_Wv, g_Wv);

    to_half<<<8192, 256>>>(H_i, p_Hi, (size_t)MPROJ * Dd / 4);
    to_half<<<8192, 256>>>(H_j, p_Hj, (size_t)MPROJ * Dd / 4);
    to_half<<<256, 256>>>(Wq, p_Wq, (size_t)Dd * Dd / 4);
    to_half<<<256, 256>>>(Wk, p_Wk, (size_t)Dd * Dd / 4);
    to_half<<<256, 256>>>(Wv, p_Wv, (size_t)Dd * Dd / 4);

    const int proj_shmem = 3 * 32768;  // 96KB
    cudaFuncSetAttribute(proj_gemm, cudaFuncAttributeMaxDynamicSharedMemorySize, proj_shmem);

    dim3 blk(256);
    dim3 gproj(4, MPROJ / 128, 1);     // x = n-tile (L2-shared A), y = m-tile
    proj_gemm<<<gproj, blk, proj_shmem>>>(p_Hi, p_Wq, bq, 0);
    proj_gemm<<<gproj, blk, proj_shmem>>>(p_Hj, p_Wk, bk, 1);
    proj_gemm<<<gproj, blk, proj_shmem>>>(p_Hj, p_Wv, bv, 2);

    // P 128KB + 96KB stage region + rsum(2KB) + invl(512B) = 231936 B
    const int attn_shmem = 131072 + 98304 + 2048 + 512;
    cudaFuncSetAttribute(attn_fused, cudaFuncAttributeMaxDynamicSharedMemorySize, attn_shmem);
    attn_fused<<<dim3(4, NHEADS), 512, attn_shmem>>>(out, lg, lt);
}